// round 8
// baseline (speedup 1.0000x reference)
#include <cuda_runtime.h>
#include <math.h>
#include <stdint.h>

#define SEQ   4096
#define MODEL 2048
#define NH    16
#define HD    128
#define QKV_N (3*MODEL)

// Scratch (__device__ globals: allocation-free rule)
__device__ float g_hidden[(size_t)SEQ * QKV_N];
__device__ float g_z[(size_t)SEQ * MODEL];
__device__ float g_xr[(size_t)SEQ * MODEL];     // rounded x      [SEQ][MODEL]
__device__ float g_wa[(size_t)MODEL * QKV_N];   // rounded w_attn [MODEL][QKV_N]
__device__ float g_wp[(size_t)MODEL * MODEL];   // rounded w_proj [MODEL][MODEL]

__device__ __forceinline__ uint32_t f2tf32(float f) {
    uint32_t u; asm("cvt.rna.tf32.f32 %0, %1;" : "=r"(u) : "f"(f)); return u;
}
__device__ __forceinline__ void mma_tf32(float* c, const uint32_t* a,
                                         uint32_t b0, uint32_t b1) {
    asm volatile(
        "mma.sync.aligned.m16n8k8.row.col.f32.tf32.tf32.f32 "
        "{%0,%1,%2,%3}, {%4,%5,%6,%7}, {%8,%9}, {%0,%1,%2,%3};\n"
        : "+f"(c[0]), "+f"(c[1]), "+f"(c[2]), "+f"(c[3])
        : "r"(a[0]), "r"(a[1]), "r"(a[2]), "r"(a[3]), "r"(b0), "r"(b1));
}
__device__ __forceinline__ void cp16(uint32_t dst, const void* src) {
    asm volatile("cp.async.cg.shared.global [%0], [%1], 16;\n" :: "r"(dst), "l"(src));
}
__device__ __forceinline__ void cp_commit() { asm volatile("cp.async.commit_group;\n"); }
template<int N> __device__ __forceinline__ void cp_wait() {
    asm volatile("cp.async.wait_group %0;\n" :: "n"(N));
}
__device__ __forceinline__ uint32_t smem_u32(const void* p) {
    uint32_t a;
    asm("{ .reg .u64 t; cvta.to.shared.u64 t, %1; cvt.u32.u64 %0, t; }"
        : "=r"(a) : "l"(p));
    return a;
}

// ---------------------------------------------------------------------------
// Pre-round fp32 -> tf32 (RNA)
// ---------------------------------------------------------------------------
__global__ void round_tf32_kernel(const float* __restrict__ in,
                                  float* __restrict__ out, int n) {
    int i = (blockIdx.x * blockDim.x + threadIdx.x) * 4;
    int stride = gridDim.x * blockDim.x * 4;
    for (; i < n; i += stride) {
        float4 v = *(const float4*)(in + i);
        *(uint4*)(out + i) = make_uint4(f2tf32(v.x), f2tf32(v.y),
                                        f2tf32(v.z), f2tf32(v.w));
    }
}

// ---------------------------------------------------------------------------
// tf32 GEMM: C[M,N] = A[M,K]@B[K,N] + bias. A,B pre-rounded tf32 bits.
// Block 256x128, BK=16, 512 thr = 16 warps (8x2), warp tile 32x64 (64 accums).
// 4 warps/SMSP for latency hiding; cp.async 4-stage.
// ---------------------------------------------------------------------------
#define GS 4
#define ASTRIDE 20
#define BSTRIDE 136
#define A_TILE (256*ASTRIDE)
#define B_TILE (16*BSTRIDE)
#define GEMM_SMEM ((GS*(A_TILE+B_TILE))*4)

template<bool ROUND_OUT>
__global__ __launch_bounds__(512, 1) void gemm_tf32(
    const float* __restrict__ A, const float* __restrict__ B,
    const float* __restrict__ bias, float* __restrict__ C,
    int M, int N, int K)
{
    extern __shared__ uint32_t gsm[];
    uint32_t* As = gsm;                  // [GS][256][ASTRIDE]  ([m][k])
    uint32_t* Bs = gsm + GS*A_TILE;      // [GS][16][BSTRIDE]   ([k][n])

    const int tid  = threadIdx.x;
    const int lane = tid & 31;
    const int warp = tid >> 5;
    const int ra   = lane >> 2;
    const int kq   = lane & 3;
    const int m0 = (warp >> 1) * 32;     // 8 m-slices of 32
    const int n0 = (warp & 1) * 64;      // 2 n-slices of 64
    const int row0 = blockIdx.y * 256, col0 = blockIdx.x * 128;

    const int art = tid >> 2, acol = (tid & 3) * 4;   // A: 2 rows x 16B
    const int bkr = tid >> 5, bcol = (tid & 31) * 4;  // B: 1 slot of 16B

    uint32_t asA = (uint32_t)__cvta_generic_to_shared(As);
    uint32_t asB = (uint32_t)__cvta_generic_to_shared(Bs);
    const int niter = K >> 4;

    auto issue = [&](int t) {
        int st = t & (GS - 1);
        const float* ap = A + (size_t)(row0 + art) * K + t*16 + acol;
        uint32_t ad = asA + (uint32_t)(st*A_TILE + art*ASTRIDE + acol) * 4u;
        cp16(ad, ap);
        cp16(ad + 128u*ASTRIDE*4u, ap + (size_t)128 * K);
        const float* bp = B + (size_t)(t*16 + bkr) * N + col0 + bcol;
        uint32_t bd = asB + (uint32_t)(st*B_TILE + bkr*BSTRIDE + bcol) * 4u;
        cp16(bd, bp);
    };

    #pragma unroll
    for (int s = 0; s < GS - 1; s++) { issue(s); cp_commit(); }

    float c[2][8][4];
    #pragma unroll
    for (int mi = 0; mi < 2; mi++)
        #pragma unroll
        for (int ni = 0; ni < 8; ni++)
            #pragma unroll
            for (int r = 0; r < 4; r++) c[mi][ni][r] = 0.f;

    for (int i = 0; i < niter; i++) {
        cp_wait<GS-2>();
        __syncthreads();
        if (i + GS - 1 < niter) issue(i + GS - 1);
        cp_commit();

        const uint32_t* Ab = As + (size_t)(i & (GS-1)) * A_TILE;
        const uint32_t* Bb = Bs + (size_t)(i & (GS-1)) * B_TILE;

        #pragma unroll
        for (int kk = 0; kk < 16; kk += 8) {
            uint32_t af[2][4];
            #pragma unroll
            for (int mi = 0; mi < 2; mi++) {
                const uint32_t* p = Ab + (m0 + mi*16 + ra)*ASTRIDE + kk + kq;
                af[mi][0] = p[0];
                af[mi][1] = p[8*ASTRIDE];
                af[mi][2] = p[4];
                af[mi][3] = p[8*ASTRIDE + 4];
            }
            uint32_t bf[8][2];
            #pragma unroll
            for (int ni = 0; ni < 8; ni++) {
                const uint32_t* bp = Bb + (kk + kq)*BSTRIDE + n0 + ni*8 + ra;
                bf[ni][0] = bp[0];
                bf[ni][1] = bp[4*BSTRIDE];
            }
            #pragma unroll
            for (int ni = 0; ni < 8; ni++)
                #pragma unroll
                for (int mi = 0; mi < 2; mi++)
                    mma_tf32(c[mi][ni], af[mi], bf[ni][0], bf[ni][1]);
        }
    }

    #pragma unroll
    for (int ni = 0; ni < 8; ni++) {
        int cc = col0 + n0 + ni*8 + 2*kq;
        float2 bb = *(const float2*)(bias + cc);
        #pragma unroll
        for (int mi = 0; mi < 2; mi++) {
            int r = row0 + m0 + mi*16 + ra;
            float o0 = c[mi][ni][0] + bb.x, o1 = c[mi][ni][1] + bb.y;
            float o2 = c[mi][ni][2] + bb.x, o3 = c[mi][ni][3] + bb.y;
            if (ROUND_OUT) {
                o0 = __uint_as_float(f2tf32(o0)); o1 = __uint_as_float(f2tf32(o1));
                o2 = __uint_as_float(f2tf32(o2)); o3 = __uint_as_float(f2tf32(o3));
            }
            *(float2*)(C + (size_t)r * N + cc)       = make_float2(o0, o1);
            *(float2*)(C + (size_t)(r + 8) * N + cc) = make_float2(o2, o3);
        }
    }
}

// ---------------------------------------------------------------------------
// tf32 flash attention (causal). Q block 128 (fragments in REGISTERS),
// key tile 64, K/V double-buffered cp.async pipeline (prefetch kb+2 while
// computing kb). 8 warps x 16 q-rows. hidden pre-rounded tf32. (unchanged R7)
// ---------------------------------------------------------------------------
#define KS_S 132
#define VS_S 136
#define PS_S 68
#define FL_SMEM ((2*64*KS_S + 2*64*VS_S + 128*PS_S)*4)

__global__ __launch_bounds__(256, 1) void flash_tf32(
    const float* __restrict__ hidden, float* __restrict__ z)
{
    extern __shared__ uint32_t sm[];
    uint32_t* Ks = sm;                    // [2][64][KS_S]
    uint32_t* Vs = Ks + 2*64*KS_S;        // [2][64][VS_S]
    uint32_t* Ps = Vs + 2*64*VS_S;        // [128][PS_S]

    const int h    = blockIdx.y;
    const int qb   = (int)(gridDim.x - 1) - (int)blockIdx.x;  // heavy first
    const int tid  = threadIdx.x;
    const int lane = tid & 31;
    const int warp = tid >> 5;
    const int m0   = warp * 16;
    const int ra   = lane >> 2;
    const int kq   = lane & 3;
    const float scale = 0.08838834764831845f;  // 1/sqrt(128)

    uint32_t asK = smem_u32(Ks);
    uint32_t asV = smem_u32(Vs);

    auto load_tile = [&](int t) {
        uint32_t kb_ = asK + (uint32_t)(t & 1) * 64u*KS_S*4u;
        uint32_t vb_ = asV + (uint32_t)(t & 1) * 64u*VS_S*4u;
        #pragma unroll
        for (int i = 0; i < 8; i++) {
            int idx = tid + 256*i;
            int r = idx >> 5, d4 = (idx & 31) << 2;
            const float* kp = hidden + (size_t)(t*64 + r)*QKV_N + MODEL + h*HD + d4;
            cp16(kb_ + (uint32_t)(r*KS_S + d4)*4u, kp);
            cp16(vb_ + (uint32_t)(r*VS_S + d4)*4u, kp + MODEL);
        }
        cp_commit();
    };

    // Q fragments straight to registers (values already tf32-rounded)
    uint32_t qf[16][4];
    {
        const float* qp0 = hidden + (size_t)(qb*128 + m0 + ra)*QKV_N + h*HD;
        const float* qp1 = qp0 + (size_t)8*QKV_N;
        #pragma unroll
        for (int i = 0; i < 16; i++) {
            qf[i][0] = __float_as_uint(qp0[i*8 + kq]);
            qf[i][1] = __float_as_uint(qp1[i*8 + kq]);
            qf[i][2] = __float_as_uint(qp0[i*8 + kq + 4]);
            qf[i][3] = __float_as_uint(qp1[i*8 + kq + 4]);
        }
    }

    float m_a = -1e30f, m_b = -1e30f, l_a = 0.f, l_b = 0.f;
    float o[16][4];
    #pragma unroll
    for (int ni = 0; ni < 16; ni++)
        o[ni][0] = o[ni][1] = o[ni][2] = o[ni][3] = 0.f;

    const int qr_a = qb*128 + m0 + ra;
    const int nkb  = 2*qb + 2;

    load_tile(0);
    load_tile(1);

    for (int kb = 0; kb < nkb; kb++) {
        cp_wait<1>();          // tile kb resident (kb+1 may still be in flight)
        __syncthreads();

        const uint32_t* Kb = Ks + (kb & 1)*64*KS_S;
        const uint32_t* Vb = Vs + (kb & 1)*64*VS_S;

        // ---- S = Q @ K^T (Q from registers) ----
        float s[8][4];
        #pragma unroll
        for (int n = 0; n < 8; n++) s[n][0] = s[n][1] = s[n][2] = s[n][3] = 0.f;

        #pragma unroll
        for (int i = 0; i < 16; i++) {
            #pragma unroll
            for (int n = 0; n < 8; n++) {
                const uint32_t* kp2 = Kb + (n*8 + ra)*KS_S + i*8 + kq;
                mma_tf32(s[n], qf[i], kp2[0], kp2[4]);
            }
        }

        #pragma unroll
        for (int n = 0; n < 8; n++) {
            s[n][0] *= scale; s[n][1] *= scale;
            s[n][2] *= scale; s[n][3] *= scale;
        }

        // ---- causal mask (near-diagonal tiles only) ----
        if (kb >= 2*qb) {
            #pragma unroll
            for (int n = 0; n < 8; n++) {
                int col = kb*64 + n*8 + 2*kq;
                if (col     > qr_a)     s[n][0] = -1e30f;
                if (col + 1 > qr_a)     s[n][1] = -1e30f;
                if (col     > qr_a + 8) s[n][2] = -1e30f;
                if (col + 1 > qr_a + 8) s[n][3] = -1e30f;
            }
        }

        // ---- online softmax ----
        float mxa = -1e30f, mxb = -1e30f;
        #pragma unroll
        for (int n = 0; n < 8; n++) {
            mxa = fmaxf(mxa, fmaxf(s[n][0], s[n][1]));
            mxb = fmaxf(mxb, fmaxf(s[n][2], s[n][3]));
        }
        mxa = fmaxf(mxa, __shfl_xor_sync(0xffffffffu, mxa, 1));
        mxa = fmaxf(mxa, __shfl_xor_sync(0xffffffffu, mxa, 2));
        mxb = fmaxf(mxb, __shfl_xor_sync(0xffffffffu, mxb, 1));
        mxb = fmaxf(mxb, __shfl_xor_sync(0xffffffffu, mxb, 2));

        float mna = fmaxf(m_a, mxa), mnb = fmaxf(m_b, mxb);
        float alpha_a = __expf(m_a - mna), alpha_b = __expf(m_b - mnb);
        float suma = 0.f, sumb = 0.f;
        #pragma unroll
        for (int n = 0; n < 8; n++) {
            float p0 = __expf(s[n][0] - mna), p1 = __expf(s[n][1] - mna);
            float p2 = __expf(s[n][2] - mnb), p3 = __expf(s[n][3] - mnb);
            suma += p0 + p1; sumb += p2 + p3;
            uint32_t* pp = Ps + (m0 + ra)*PS_S + n*8 + 2*kq;
            pp[0] = f2tf32(p0); pp[1] = f2tf32(p1);
            pp[8*PS_S] = f2tf32(p2); pp[8*PS_S + 1] = f2tf32(p3);
        }
        suma += __shfl_xor_sync(0xffffffffu, suma, 1);
        suma += __shfl_xor_sync(0xffffffffu, suma, 2);
        sumb += __shfl_xor_sync(0xffffffffu, sumb, 1);
        sumb += __shfl_xor_sync(0xffffffffu, sumb, 2);
        l_a = l_a * alpha_a + suma;
        l_b = l_b * alpha_b + sumb;
        m_a = mna; m_b = mnb;
        #pragma unroll
        for (int ni = 0; ni < 16; ni++) {
            o[ni][0] *= alpha_a; o[ni][1] *= alpha_a;
            o[ni][2] *= alpha_b; o[ni][3] *= alpha_b;
        }
        __syncwarp();

        // ---- O += P @ V ----
        #pragma unroll
        for (int k0 = 0; k0 < 64; k0 += 8) {
            uint32_t a[4];
            const uint32_t* pp = Ps + (m0 + ra)*PS_S + k0 + kq;
            a[0] = pp[0]; a[1] = pp[8*PS_S]; a[2] = pp[4]; a[3] = pp[8*PS_S + 4];
            #pragma unroll
            for (int ni = 0; ni < 16; ni++) {
                const uint32_t* vp = Vb + (k0 + kq)*VS_S + ni*8 + ra;
                mma_tf32(o[ni], a, vp[0], vp[4*VS_S]);
            }
        }

        __syncthreads();           // all warps done with buf[kb&1]
        if (kb + 2 < nkb) load_tile(kb + 2);
        else              cp_commit();   // dummy group keeps wait<1> semantics
    }

    // ---- normalize + write z rounded (proj GEMM reads cvt-free) ----
    float inva = 1.f / l_a, invb = 1.f / l_b;
    #pragma unroll
    for (int ni = 0; ni < 16; ni++) {
        int cc = h*HD + ni*8 + 2*kq;
        int r  = qb*128 + m0 + ra;
        uint2 v0 = make_uint2(f2tf32(o[ni][0]*inva), f2tf32(o[ni][1]*inva));
        uint2 v1 = make_uint2(f2tf32(o[ni][2]*invb), f2tf32(o[ni][3]*invb));
        *(uint2*)(z + (size_t)r * MODEL + cc)       = v0;
        *(uint2*)(z + (size_t)(r + 8) * MODEL + cc) = v1;
    }
}

// ---------------------------------------------------------------------------
extern "C" void kernel_launch(void* const* d_in, const int* in_sizes, int n_in,
                              void* d_out, int out_size)
{
    const float* x      = (const float*)d_in[0];
    const float* w_attn = (const float*)d_in[1];
    const float* b_attn = (const float*)d_in[2];
    const float* w_proj = (const float*)d_in[3];
    const float* b_proj = (const float*)d_in[4];
    float* out = (float*)d_out;

    float *hid, *z, *xr, *wa, *wp;
    cudaGetSymbolAddress((void**)&hid, g_hidden);
    cudaGetSymbolAddress((void**)&z,   g_z);
    cudaGetSymbolAddress((void**)&xr,  g_xr);
    cudaGetSymbolAddress((void**)&wa,  g_wa);
    cudaGetSymbolAddress((void**)&wp,  g_wp);

    cudaFuncSetAttribute(gemm_tf32<true>,
                         cudaFuncAttributeMaxDynamicSharedMemorySize, GEMM_SMEM);
    cudaFuncSetAttribute(gemm_tf32<false>,
                         cudaFuncAttributeMaxDynamicSharedMemorySize, GEMM_SMEM);
    cudaFuncSetAttribute(flash_tf32,
                         cudaFuncAttributeMaxDynamicSharedMemorySize, FL_SMEM);

    // 0) pre-round GEMM operands (numerics-identical to per-load cvt)
    round_tf32_kernel<<<2048, 256>>>(x,      xr, SEQ*MODEL);
    round_tf32_kernel<<<2048, 256>>>(w_attn, wa, MODEL*QKV_N);
    round_tf32_kernel<<<2048, 256>>>(w_proj, wp, MODEL*MODEL);

    // 1) QKV projection (rounded output feeds flash cvt-free)
    gemm_tf32<true><<<dim3(QKV_N/128, SEQ/256), 512, GEMM_SMEM>>>(
        xr, wa, b_attn, hid, SEQ, QKV_N, MODEL);

    // 2) causal multi-head attention (writes rounded z)
    flash_tf32<<<dim3(SEQ/128, NH), 256, FL_SMEM>>>(hid, z);

    // 3) output projection (fp32 output)
    gemm_tf32<false><<<dim3(MODEL/128, SEQ/256), 512, GEMM_SMEM>>>(
        z, wp, b_proj, out, SEQ, MODEL, MODEL);
}

// round 10
// speedup vs baseline: 1.3284x; 1.3284x over previous
#include <cuda_runtime.h>
#include <math.h>
#include <stdint.h>

#define SEQ   4096
#define MODEL 2048
#define NH    16
#define HD    128
#define QKV_N (3*MODEL)

// Scratch (__device__ globals: allocation-free rule)
__device__ float g_hidden[(size_t)SEQ * QKV_N];
__device__ float g_z[(size_t)SEQ * MODEL];
__device__ float g_xr[(size_t)SEQ * MODEL];     // rounded x          [SEQ][MODEL]
__device__ float g_wa[(size_t)MODEL * QKV_N];   // rounded w_attn^T   [QKV_N][MODEL]
__device__ float g_wp[(size_t)MODEL * MODEL];   // rounded w_proj^T   [MODEL][MODEL]

__device__ __forceinline__ uint32_t f2tf32(float f) {
    uint32_t u; asm("cvt.rna.tf32.f32 %0, %1;" : "=r"(u) : "f"(f)); return u;
}
__device__ __forceinline__ void mma_tf32(float* c, const uint32_t* a,
                                         uint32_t b0, uint32_t b1) {
    asm volatile(
        "mma.sync.aligned.m16n8k8.row.col.f32.tf32.tf32.f32 "
        "{%0,%1,%2,%3}, {%4,%5,%6,%7}, {%8,%9}, {%0,%1,%2,%3};\n"
        : "+f"(c[0]), "+f"(c[1]), "+f"(c[2]), "+f"(c[3])
        : "r"(a[0]), "r"(a[1]), "r"(a[2]), "r"(a[3]), "r"(b0), "r"(b1));
}
__device__ __forceinline__ void ldsm4(uint32_t* r, uint32_t addr) {
    asm volatile("ldmatrix.sync.aligned.m8n8.x4.shared.b16 {%0,%1,%2,%3}, [%4];"
        : "=r"(r[0]), "=r"(r[1]), "=r"(r[2]), "=r"(r[3]) : "r"(addr));
}
__device__ __forceinline__ void cp16(uint32_t dst, const void* src) {
    asm volatile("cp.async.cg.shared.global [%0], [%1], 16;\n" :: "r"(dst), "l"(src));
}
__device__ __forceinline__ void cp_commit() { asm volatile("cp.async.commit_group;\n"); }
template<int N> __device__ __forceinline__ void cp_wait() {
    asm volatile("cp.async.wait_group %0;\n" :: "n"(N));
}
__device__ __forceinline__ uint32_t smem_u32(const void* p) {
    uint32_t a;
    asm("{ .reg .u64 t; cvta.to.shared.u64 t, %1; cvt.u32.u64 %0, t; }"
        : "=r"(a) : "l"(p));
    return a;
}

// ---------------------------------------------------------------------------
// Prep kernels
// ---------------------------------------------------------------------------
__global__ void round_tf32_kernel(const float* __restrict__ in,
                                  float* __restrict__ out, int n) {
    int i = (blockIdx.x * blockDim.x + threadIdx.x) * 4;
    int stride = gridDim.x * blockDim.x * 4;
    for (; i < n; i += stride) {
        float4 v = *(const float4*)(in + i);
        *(uint4*)(out + i) = make_uint4(f2tf32(v.x), f2tf32(v.y),
                                        f2tf32(v.z), f2tf32(v.w));
    }
}

// out[c][r] = rna(in[r][c]); in is [R][C]
__global__ void transpose_round(const float* __restrict__ in,
                                float* __restrict__ out, int R, int C) {
    __shared__ float tile[32][33];
    int c0 = blockIdx.x * 32, r0 = blockIdx.y * 32;
    int tx = threadIdx.x, ty = threadIdx.y;
    #pragma unroll
    for (int i = 0; i < 32; i += 8)
        tile[ty + i][tx] = in[(size_t)(r0 + ty + i) * C + c0 + tx];
    __syncthreads();
    #pragma unroll
    for (int i = 0; i < 32; i += 8)
        out[(size_t)(c0 + ty + i) * R + r0 + tx] =
            __uint_as_float(f2tf32(tile[tx][ty + i]));
}

// ---------------------------------------------------------------------------
// tf32 GEMM: C[M,N] = A[M,K] @ Bt[N,K]^T + bias. A,Bt pre-rounded tf32 bits.
// Block 128x128, BK=16, 256 thr = 8 warps (2x4), warp tile 64x32.
// Both A and Bt tiles stored [row][k] (+4 pad); fragments via ldmatrix.x4.
// cp.async 4-stage; __launch_bounds__(256,2) -> 2 CTAs/SM interleave barriers.
// ---------------------------------------------------------------------------
#define GS 4
#define RSTRIDE 20                       // 16 k-words + 4 pad
#define A_TILE (128*RSTRIDE)
#define STAGE  (2*A_TILE)
#define GEMM_SMEM (GS*STAGE*4)           // 80 KB

template<bool ROUND_OUT>
__global__ __launch_bounds__(256, 2) void gemm_tf32(
    const float* __restrict__ A, const float* __restrict__ Bt,
    const float* __restrict__ bias, float* __restrict__ C,
    int M, int N, int K)
{
    extern __shared__ uint32_t gsm[];
    const int tid  = threadIdx.x;
    const int lane = tid & 31;
    const int warp = tid >> 5;
    const int ra   = lane >> 2;
    const int kq   = lane & 3;
    const int m0 = (warp >> 2) * 64;     // 2 m-slices of 64
    const int n0 = (warp & 3) * 32;      // 4 n-slices of 32
    const int row0 = blockIdx.y * 128, col0 = blockIdx.x * 128;

    // ldmatrix per-lane row/col offsets
    const int lrA = lane & 15;               // A: row within m16
    const int lcA = (lane >> 4) * 4;         // A: k offset 0/4
    const int lrB = ((lane >> 4) << 3) + (lane & 7);  // B: row within n16
    const int lcB = ((lane >> 3) & 1) * 4;   // B: k offset 0/4

    uint32_t asS = (uint32_t)__cvta_generic_to_shared(gsm);
    const int ldr = tid & 127;           // loader row
    const int ldc = tid >> 7;            // loader chunk 0/1
    const int niter = K >> 4;

    auto issue = [&](int t) {
        uint32_t sb = asS + (uint32_t)(t & (GS-1)) * STAGE * 4u;
        const float* ap = A + (size_t)(row0 + ldr) * K + t*16;
        uint32_t ad = sb + (uint32_t)(ldr * RSTRIDE) * 4u;
        cp16(ad + ldc*16u,      ap + ldc*4);
        cp16(ad + (ldc+2)*16u,  ap + (ldc+2)*4);
        const float* bp = Bt + (size_t)(col0 + ldr) * K + t*16;
        uint32_t bd = sb + (uint32_t)A_TILE*4u + (uint32_t)(ldr * RSTRIDE) * 4u;
        cp16(bd + ldc*16u,      bp + ldc*4);
        cp16(bd + (ldc+2)*16u,  bp + (ldc+2)*4);
        cp_commit();
    };

    #pragma unroll
    for (int s = 0; s < GS - 1; s++) issue(s);

    float c[4][4][4];
    #pragma unroll
    for (int mi = 0; mi < 4; mi++)
        #pragma unroll
        for (int ni = 0; ni < 4; ni++)
            #pragma unroll
            for (int r = 0; r < 4; r++) c[mi][ni][r] = 0.f;

    for (int i = 0; i < niter; i++) {
        cp_wait<GS-2>();
        __syncthreads();
        if (i + GS - 1 < niter) issue(i + GS - 1);
        else                    cp_commit();

        uint32_t sb = asS + (uint32_t)(i & (GS-1)) * STAGE * 4u;
        uint32_t Ab = sb;
        uint32_t Bb = sb + (uint32_t)A_TILE * 4u;

        #pragma unroll
        for (int kk = 0; kk < 16; kk += 8) {
            uint32_t af[4][4];
            #pragma unroll
            for (int mi = 0; mi < 4; mi++)
                ldsm4(af[mi], Ab + (uint32_t)(((m0 + mi*16 + lrA)*RSTRIDE) + kk + lcA) * 4u);
            uint32_t bf[2][4];   // bf[g] covers ni = 2g (regs 0,1) and 2g+1 (regs 2,3)
            #pragma unroll
            for (int g = 0; g < 2; g++)
                ldsm4(bf[g], Bb + (uint32_t)(((n0 + g*16 + lrB)*RSTRIDE) + kk + lcB) * 4u);
            #pragma unroll
            for (int g = 0; g < 2; g++)
                #pragma unroll
                for (int mi = 0; mi < 4; mi++) {
                    mma_tf32(c[mi][2*g],   af[mi], bf[g][0], bf[g][1]);
                    mma_tf32(c[mi][2*g+1], af[mi], bf[g][2], bf[g][3]);
                }
        }
    }

    #pragma unroll
    for (int ni = 0; ni < 4; ni++) {
        int cc = col0 + n0 + ni*8 + 2*kq;
        float2 bb = *(const float2*)(bias + cc);
        #pragma unroll
        for (int mi = 0; mi < 4; mi++) {
            int r = row0 + m0 + mi*16 + ra;
            float o0 = c[mi][ni][0] + bb.x, o1 = c[mi][ni][1] + bb.y;
            float o2 = c[mi][ni][2] + bb.x, o3 = c[mi][ni][3] + bb.y;
            if (ROUND_OUT) {
                o0 = __uint_as_float(f2tf32(o0)); o1 = __uint_as_float(f2tf32(o1));
                o2 = __uint_as_float(f2tf32(o2)); o3 = __uint_as_float(f2tf32(o3));
            }
            *(float2*)(C + (size_t)r * N + cc)       = make_float2(o0, o1);
            *(float2*)(C + (size_t)(r + 8) * N + cc) = make_float2(o2, o3);
        }
    }
}

// ---------------------------------------------------------------------------
// tf32 flash attention (causal) — unchanged from R7 (best measured).
// Q block 128 (fragments in registers), key tile 64, K/V double-buffered
// cp.async pipeline. 8 warps x 16 q-rows. hidden pre-rounded tf32.
// ---------------------------------------------------------------------------
#define KS_S 132
#define VS_S 136
#define PS_S 68
#define FL_SMEM ((2*64*KS_S + 2*64*VS_S + 128*PS_S)*4)

__global__ __launch_bounds__(256, 1) void flash_tf32(
    const float* __restrict__ hidden, float* __restrict__ z)
{
    extern __shared__ uint32_t sm[];
    uint32_t* Ks = sm;                    // [2][64][KS_S]
    uint32_t* Vs = Ks + 2*64*KS_S;        // [2][64][VS_S]
    uint32_t* Ps = Vs + 2*64*VS_S;        // [128][PS_S]

    const int h    = blockIdx.y;
    const int qb   = (int)(gridDim.x - 1) - (int)blockIdx.x;  // heavy first
    const int tid  = threadIdx.x;
    const int lane = tid & 31;
    const int warp = tid >> 5;
    const int m0   = warp * 16;
    const int ra   = lane >> 2;
    const int kq   = lane & 3;
    const float scale = 0.08838834764831845f;  // 1/sqrt(128)

    uint32_t asK = smem_u32(Ks);
    uint32_t asV = smem_u32(Vs);

    auto load_tile = [&](int t) {
        uint32_t kb_ = asK + (uint32_t)(t & 1) * 64u*KS_S*4u;
        uint32_t vb_ = asV + (uint32_t)(t & 1) * 64u*VS_S*4u;
        #pragma unroll
        for (int i = 0; i < 8; i++) {
            int idx = tid + 256*i;
            int r = idx >> 5, d4 = (idx & 31) << 2;
            const float* kp = hidden + (size_t)(t*64 + r)*QKV_N + MODEL + h*HD + d4;
            cp16(kb_ + (uint32_t)(r*KS_S + d4)*4u, kp);
            cp16(vb_ + (uint32_t)(r*VS_S + d4)*4u, kp + MODEL);
        }
        cp_commit();
    };

    // Q fragments straight to registers (values already tf32-rounded)
    uint32_t qf[16][4];
    {
        const float* qp0 = hidden + (size_t)(qb*128 + m0 + ra)*QKV_N + h*HD;
        const float* qp1 = qp0 + (size_t)8*QKV_N;
        #pragma unroll
        for (int i = 0; i < 16; i++) {
            qf[i][0] = __float_as_uint(qp0[i*8 + kq]);
            qf[i][1] = __float_as_uint(qp1[i*8 + kq]);
            qf[i][2] = __float_as_uint(qp0[i*8 + kq + 4]);
            qf[i][3] = __float_as_uint(qp1[i*8 + kq + 4]);
        }
    }

    float m_a = -1e30f, m_b = -1e30f, l_a = 0.f, l_b = 0.f;
    float o[16][4];
    #pragma unroll
    for (int ni = 0; ni < 16; ni++)
        o[ni][0] = o[ni][1] = o[ni][2] = o[ni][3] = 0.f;

    const int qr_a = qb*128 + m0 + ra;
    const int nkb  = 2*qb + 2;

    load_tile(0);
    load_tile(1);

    for (int kb = 0; kb < nkb; kb++) {
        cp_wait<1>();
        __syncthreads();

        const uint32_t* Kb = Ks + (kb & 1)*64*KS_S;
        const uint32_t* Vb = Vs + (kb & 1)*64*VS_S;

        // ---- S = Q @ K^T (Q from registers) ----
        float s[8][4];
        #pragma unroll
        for (int n = 0; n < 8; n++) s[n][0] = s[n][1] = s[n][2] = s[n][3] = 0.f;

        #pragma unroll
        for (int i = 0; i < 16; i++) {
            #pragma unroll
            for (int n = 0; n < 8; n++) {
                const uint32_t* kp2 = Kb + (n*8 + ra)*KS_S + i*8 + kq;
                mma_tf32(s[n], qf[i], kp2[0], kp2[4]);
            }
        }

        #pragma unroll
        for (int n = 0; n < 8; n++) {
            s[n][0] *= scale; s[n][1] *= scale;
            s[n][2] *= scale; s[n][3] *= scale;
        }

        if (kb >= 2*qb) {
            #pragma unroll
            for (int n = 0; n < 8; n++) {
                int col = kb*64 + n*8 + 2*kq;
                if (col     > qr_a)     s[n][0] = -1e30f;
                if (col + 1 > qr_a)     s[n][1] = -1e30f;
                if (col     > qr_a + 8) s[n][2] = -1e30f;
                if (col + 1 > qr_a + 8) s[n][3] = -1e30f;
            }
        }

        float mxa = -1e30f, mxb = -1e30f;
        #pragma unroll
        for (int n = 0; n < 8; n++) {
            mxa = fmaxf(mxa, fmaxf(s[n][0], s[n][1]));
            mxb = fmaxf(mxb, fmaxf(s[n][2], s[n][3]));
        }
        mxa = fmaxf(mxa, __shfl_xor_sync(0xffffffffu, mxa, 1));
        mxa = fmaxf(mxa, __shfl_xor_sync(0xffffffffu, mxa, 2));
        mxb = fmaxf(mxb, __shfl_xor_sync(0xffffffffu, mxb, 1));
        mxb = fmaxf(mxb, __shfl_xor_sync(0xffffffffu, mxb, 2));

        float mna = fmaxf(m_a, mxa), mnb = fmaxf(m_b, mxb);
        float alpha_a = __expf(m_a - mna), alpha_b = __expf(m_b - mnb);
        float suma = 0.f, sumb = 0.f;
        #pragma unroll
        for (int n = 0; n < 8; n++) {
            float p0 = __expf(s[n][0] - mna), p1 = __expf(s[n][1] - mna);
            float p2 = __expf(s[n][2] - mnb), p3 = __expf(s[n][3] - mnb);
            suma += p0 + p1; sumb += p2 + p3;
            uint32_t* pp = Ps + (m0 + ra)*PS_S + n*8 + 2*kq;
            pp[0] = f2tf32(p0); pp[1] = f2tf32(p1);
            pp[8*PS_S] = f2tf32(p2); pp[8*PS_S + 1] = f2tf32(p3);
        }
        suma += __shfl_xor_sync(0xffffffffu, suma, 1);
        suma += __shfl_xor_sync(0xffffffffu, suma, 2);
        sumb += __shfl_xor_sync(0xffffffffu, sumb, 1);
        sumb += __shfl_xor_sync(0xffffffffu, sumb, 2);
        l_a = l_a * alpha_a + suma;
        l_b = l_b * alpha_b + sumb;
        m_a = mna; m_b = mnb;
        #pragma unroll
        for (int ni = 0; ni < 16; ni++) {
            o[ni][0] *= alpha_a; o[ni][1] *= alpha_a;
            o[ni][2] *= alpha_b; o[ni][3] *= alpha_b;
        }
        __syncwarp();

        // ---- O += P @ V ----
        #pragma unroll
        for (int k0 = 0; k0 < 64; k0 += 8) {
            uint32_t a[4];
            const uint32_t* pp = Ps + (m0 + ra)*PS_S + k0 + kq;
            a[0] = pp[0]; a[1] = pp[8*PS_S]; a[2] = pp[4]; a[3] = pp[8*PS_S + 4];
            #pragma unroll
            for (int ni = 0; ni < 16; ni++) {
                const uint32_t* vp = Vb + (k0 + kq)*VS_S + ni*8 + ra;
                mma_tf32(o[ni], a, vp[0], vp[4*VS_S]);
            }
        }

        __syncthreads();
        if (kb + 2 < nkb) load_tile(kb + 2);
        else              cp_commit();
    }

    float inva = 1.f / l_a, invb = 1.f / l_b;
    #pragma unroll
    for (int ni = 0; ni < 16; ni++) {
        int cc = h*HD + ni*8 + 2*kq;
        int r  = qb*128 + m0 + ra;
        uint2 v0 = make_uint2(f2tf32(o[ni][0]*inva), f2tf32(o[ni][1]*inva));
        uint2 v1 = make_uint2(f2tf32(o[ni][2]*invb), f2tf32(o[ni][3]*invb));
        *(uint2*)(z + (size_t)r * MODEL + cc)       = v0;
        *(uint2*)(z + (size_t)(r + 8) * MODEL + cc) = v1;
    }
}

// ---------------------------------------------------------------------------
extern "C" void kernel_launch(void* const* d_in, const int* in_sizes, int n_in,
                              void* d_out, int out_size)
{
    const float* x      = (const float*)d_in[0];
    const float* w_attn = (const float*)d_in[1];
    const float* b_attn = (const float*)d_in[2];
    const float* w_proj = (const float*)d_in[3];
    const float* b_proj = (const float*)d_in[4];
    float* out = (float*)d_out;

    float *hid, *z, *xr, *wa, *wp;
    cudaGetSymbolAddress((void**)&hid, g_hidden);
    cudaGetSymbolAddress((void**)&z,   g_z);
    cudaGetSymbolAddress((void**)&xr,  g_xr);
    cudaGetSymbolAddress((void**)&wa,  g_wa);
    cudaGetSymbolAddress((void**)&wp,  g_wp);

    cudaFuncSetAttribute(gemm_tf32<true>,
                         cudaFuncAttributeMaxDynamicSharedMemorySize, GEMM_SMEM);
    cudaFuncSetAttribute(gemm_tf32<false>,
                         cudaFuncAttributeMaxDynamicSharedMemorySize, GEMM_SMEM);
    cudaFuncSetAttribute(flash_tf32,
                         cudaFuncAttributeMaxDynamicSharedMemorySize, FL_SMEM);

    // 0) prep: round x; transpose+round weights to [N][K] for ldmatrix B path
    round_tf32_kernel<<<2048, 256>>>(x, xr, SEQ*MODEL);
    transpose_round<<<dim3(QKV_N/32, MODEL/32), dim3(32, 8)>>>(w_attn, wa, MODEL, QKV_N);
    transpose_round<<<dim3(MODEL/32, MODEL/32), dim3(32, 8)>>>(w_proj, wp, MODEL, MODEL);

    // 1) QKV projection (rounded output feeds flash cvt-free)
    gemm_tf32<true><<<dim3(QKV_N/128, SEQ/128), 256, GEMM_SMEM>>>(
        xr, wa, b_attn, hid, SEQ, QKV_N, MODEL);

    // 2) causal multi-head attention (writes rounded z)
    flash_tf32<<<dim3(SEQ/128, NH), 256, FL_SMEM>>>(hid, z);

    // 3) output projection (fp32 output)
    gemm_tf32<false><<<dim3(MODEL/128, SEQ/128), 256, GEMM_SMEM>>>(
        z, wp, b_proj, out, SEQ, MODEL, MODEL);
}

// round 11
// speedup vs baseline: 1.5985x; 1.2033x over previous
#include <cuda_runtime.h>
#include <math.h>
#include <stdint.h>

#define SEQ   4096
#define MODEL 2048
#define NH    16
#define HD    128
#define QKV_N (3*MODEL)

// Scratch (__device__ globals: allocation-free rule)
__device__ float g_hidden[(size_t)SEQ * QKV_N];
__device__ float g_z[(size_t)SEQ * MODEL];
__device__ float g_xr[(size_t)SEQ * MODEL];     // rounded x      [SEQ][MODEL]
__device__ float g_wa[(size_t)MODEL * QKV_N];   // rounded w_attn [MODEL][QKV_N]
__device__ float g_wp[(size_t)MODEL * MODEL];   // rounded w_proj [MODEL][MODEL]

__device__ __forceinline__ uint32_t f2tf32(float f) {
    uint32_t u; asm("cvt.rna.tf32.f32 %0, %1;" : "=r"(u) : "f"(f)); return u;
}
__device__ __forceinline__ void mma_tf32(float* c, const uint32_t* a,
                                         uint32_t b0, uint32_t b1) {
    asm volatile(
        "mma.sync.aligned.m16n8k8.row.col.f32.tf32.tf32.f32 "
        "{%0,%1,%2,%3}, {%4,%5,%6,%7}, {%8,%9}, {%0,%1,%2,%3};\n"
        : "+f"(c[0]), "+f"(c[1]), "+f"(c[2]), "+f"(c[3])
        : "r"(a[0]), "r"(a[1]), "r"(a[2]), "r"(a[3]), "r"(b0), "r"(b1));
}
__device__ __forceinline__ void cp16(uint32_t dst, const void* src) {
    asm volatile("cp.async.cg.shared.global [%0], [%1], 16;\n" :: "r"(dst), "l"(src));
}
__device__ __forceinline__ void cp_commit() { asm volatile("cp.async.commit_group;\n"); }
template<int N> __device__ __forceinline__ void cp_wait() {
    asm volatile("cp.async.wait_group %0;\n" :: "n"(N));
}
__device__ __forceinline__ uint32_t smem_u32(const void* p) {
    uint32_t a;
    asm("{ .reg .u64 t; cvta.to.shared.u64 t, %1; cvt.u32.u64 %0, t; }"
        : "=r"(a) : "l"(p));
    return a;
}

// ---------------------------------------------------------------------------
// Pre-round fp32 -> tf32 (RNA)
// ---------------------------------------------------------------------------
__global__ void round_tf32_kernel(const float* __restrict__ in,
                                  float* __restrict__ out, int n) {
    int i = (blockIdx.x * blockDim.x + threadIdx.x) * 4;
    int stride = gridDim.x * blockDim.x * 4;
    for (; i < n; i += stride) {
        float4 v = *(const float4*)(in + i);
        *(uint4*)(out + i) = make_uint4(f2tf32(v.x), f2tf32(v.y),
                                        f2tf32(v.z), f2tf32(v.w));
    }
}

// ---------------------------------------------------------------------------
// tf32 GEMM (R5 exact — best measured): C = A@B + bias, A,B pre-rounded.
// 128x128 tile, BK=16, 256 thr (2x4 warps, 64x32 warp tile), cp.async 4-stage,
// scalar fragment LDS, 2 CTAs/SM.
// ---------------------------------------------------------------------------
#define GS 4
#define ASTRIDE 20
#define BSTRIDE 136
#define A_TILE (128*ASTRIDE)
#define B_TILE (16*BSTRIDE)
#define GEMM_SMEM ((GS*(A_TILE+B_TILE))*4)

template<bool ROUND_OUT>
__global__ __launch_bounds__(256, 2) void gemm_tf32(
    const float* __restrict__ A, const float* __restrict__ B,
    const float* __restrict__ bias, float* __restrict__ C,
    int M, int N, int K)
{
    extern __shared__ uint32_t gsm[];
    uint32_t* As = gsm;                  // [GS][128][ASTRIDE]  ([m][k])
    uint32_t* Bs = gsm + GS*A_TILE;      // [GS][16][BSTRIDE]   ([k][n])

    const int tid  = threadIdx.x;
    const int lane = tid & 31;
    const int warp = tid >> 5;
    const int m0 = (warp >> 2) * 64;
    const int n0 = (warp & 3) * 32;
    const int row0 = blockIdx.y * 128, col0 = blockIdx.x * 128;

    const int art = tid >> 2, acol = (tid & 3) * 4;
    const int bkr = tid >> 4, bcol = (tid & 15) * 8;

    uint32_t asA = (uint32_t)__cvta_generic_to_shared(As);
    uint32_t asB = (uint32_t)__cvta_generic_to_shared(Bs);
    const int niter = K >> 4;

    auto issue = [&](int t) {
        int st = t & (GS - 1);
        const float* ap = A + (size_t)(row0 + art) * K + t*16 + acol;
        uint32_t ad = asA + (uint32_t)(st*A_TILE + art*ASTRIDE + acol) * 4u;
        cp16(ad, ap);
        cp16(ad + 64u*ASTRIDE*4u, ap + (size_t)64 * K);
        const float* bp = B + (size_t)(t*16 + bkr) * N + col0 + bcol;
        uint32_t bd = asB + (uint32_t)(st*B_TILE + bkr*BSTRIDE + bcol) * 4u;
        cp16(bd, bp);
        cp16(bd + 16u, bp + 4);
    };

    #pragma unroll
    for (int s = 0; s < GS - 1; s++) { issue(s); cp_commit(); }

    float c[4][4][4];
    #pragma unroll
    for (int mi = 0; mi < 4; mi++)
        #pragma unroll
        for (int ni = 0; ni < 4; ni++)
            #pragma unroll
            for (int r = 0; r < 4; r++) c[mi][ni][r] = 0.f;

    for (int i = 0; i < niter; i++) {
        cp_wait<GS-2>();
        __syncthreads();   // also protects stage (i-1)%4 == (i+3)%4 for issue below
        if (i + GS - 1 < niter) issue(i + GS - 1);
        cp_commit();

        const uint32_t* Ab = As + (size_t)(i & (GS-1)) * A_TILE;
        const uint32_t* Bb = Bs + (size_t)(i & (GS-1)) * B_TILE;

        #pragma unroll
        for (int kk = 0; kk < 16; kk += 8) {
            uint32_t af[4][4];
            #pragma unroll
            for (int mi = 0; mi < 4; mi++) {
                const uint32_t* p = Ab + (m0 + mi*16 + (lane>>2))*ASTRIDE + kk + (lane&3);
                af[mi][0] = p[0];
                af[mi][1] = p[8*ASTRIDE];
                af[mi][2] = p[4];
                af[mi][3] = p[8*ASTRIDE + 4];
            }
            #pragma unroll
            for (int ni = 0; ni < 4; ni++) {
                const uint32_t* bp = Bb + (kk + (lane&3))*BSTRIDE + n0 + ni*8 + (lane>>2);
                uint32_t b0 = bp[0];
                uint32_t b1 = bp[4*BSTRIDE];
                #pragma unroll
                for (int mi = 0; mi < 4; mi++)
                    mma_tf32(c[mi][ni], af[mi], b0, b1);
            }
        }
    }

    #pragma unroll
    for (int ni = 0; ni < 4; ni++) {
        int cc = col0 + n0 + ni*8 + 2*(lane & 3);
        float2 bb = *(const float2*)(bias + cc);
        #pragma unroll
        for (int mi = 0; mi < 4; mi++) {
            int r = row0 + m0 + mi*16 + (lane >> 2);
            float o0 = c[mi][ni][0] + bb.x, o1 = c[mi][ni][1] + bb.y;
            float o2 = c[mi][ni][2] + bb.x, o3 = c[mi][ni][3] + bb.y;
            if (ROUND_OUT) {
                o0 = __uint_as_float(f2tf32(o0)); o1 = __uint_as_float(f2tf32(o1));
                o2 = __uint_as_float(f2tf32(o2)); o3 = __uint_as_float(f2tf32(o3));
            }
            *(float2*)(C + (size_t)r * N + cc)       = make_float2(o0, o1);
            *(float2*)(C + (size_t)(r + 8) * N + cc) = make_float2(o2, o3);
        }
    }
}

// ---------------------------------------------------------------------------
// tf32 flash attention (causal) — R7 exact (best measured).
// Q block 128 (fragments in registers), key tile 64, K/V double-buffered
// cp.async pipeline. 8 warps x 16 q-rows. hidden pre-rounded tf32.
// ---------------------------------------------------------------------------
#define KS_S 132
#define VS_S 136
#define PS_S 68
#define FL_SMEM ((2*64*KS_S + 2*64*VS_S + 128*PS_S)*4)

__global__ __launch_bounds__(256, 1) void flash_tf32(
    const float* __restrict__ hidden, float* __restrict__ z)
{
    extern __shared__ uint32_t sm[];
    uint32_t* Ks = sm;                    // [2][64][KS_S]
    uint32_t* Vs = Ks + 2*64*KS_S;        // [2][64][VS_S]
    uint32_t* Ps = Vs + 2*64*VS_S;        // [128][PS_S]

    const int h    = blockIdx.y;
    const int qb   = (int)(gridDim.x - 1) - (int)blockIdx.x;  // heavy first
    const int tid  = threadIdx.x;
    const int lane = tid & 31;
    const int warp = tid >> 5;
    const int m0   = warp * 16;
    const int ra   = lane >> 2;
    const int kq   = lane & 3;
    const float scale = 0.08838834764831845f;  // 1/sqrt(128)

    uint32_t asK = smem_u32(Ks);
    uint32_t asV = smem_u32(Vs);

    auto load_tile = [&](int t) {
        uint32_t kb_ = asK + (uint32_t)(t & 1) * 64u*KS_S*4u;
        uint32_t vb_ = asV + (uint32_t)(t & 1) * 64u*VS_S*4u;
        #pragma unroll
        for (int i = 0; i < 8; i++) {
            int idx = tid + 256*i;
            int r = idx >> 5, d4 = (idx & 31) << 2;
            const float* kp = hidden + (size_t)(t*64 + r)*QKV_N + MODEL + h*HD + d4;
            cp16(kb_ + (uint32_t)(r*KS_S + d4)*4u, kp);
            cp16(vb_ + (uint32_t)(r*VS_S + d4)*4u, kp + MODEL);
        }
        cp_commit();
    };

    // Q fragments straight to registers (values already tf32-rounded)
    uint32_t qf[16][4];
    {
        const float* qp0 = hidden + (size_t)(qb*128 + m0 + ra)*QKV_N + h*HD;
        const float* qp1 = qp0 + (size_t)8*QKV_N;
        #pragma unroll
        for (int i = 0; i < 16; i++) {
            qf[i][0] = __float_as_uint(qp0[i*8 + kq]);
            qf[i][1] = __float_as_uint(qp1[i*8 + kq]);
            qf[i][2] = __float_as_uint(qp0[i*8 + kq + 4]);
            qf[i][3] = __float_as_uint(qp1[i*8 + kq + 4]);
        }
    }

    float m_a = -1e30f, m_b = -1e30f, l_a = 0.f, l_b = 0.f;
    float o[16][4];
    #pragma unroll
    for (int ni = 0; ni < 16; ni++)
        o[ni][0] = o[ni][1] = o[ni][2] = o[ni][3] = 0.f;

    const int qr_a = qb*128 + m0 + ra;
    const int nkb  = 2*qb + 2;

    load_tile(0);
    load_tile(1);

    for (int kb = 0; kb < nkb; kb++) {
        cp_wait<1>();
        __syncthreads();

        const uint32_t* Kb = Ks + (kb & 1)*64*KS_S;
        const uint32_t* Vb = Vs + (kb & 1)*64*VS_S;

        // ---- S = Q @ K^T (Q from registers) ----
        float s[8][4];
        #pragma unroll
        for (int n = 0; n < 8; n++) s[n][0] = s[n][1] = s[n][2] = s[n][3] = 0.f;

        #pragma unroll
        for (int i = 0; i < 16; i++) {
            #pragma unroll
            for (int n = 0; n < 8; n++) {
                const uint32_t* kp2 = Kb + (n*8 + ra)*KS_S + i*8 + kq;
                mma_tf32(s[n], qf[i], kp2[0], kp2[4]);
            }
        }

        #pragma unroll
        for (int n = 0; n < 8; n++) {
            s[n][0] *= scale; s[n][1] *= scale;
            s[n][2] *= scale; s[n][3] *= scale;
        }

        if (kb >= 2*qb) {
            #pragma unroll
            for (int n = 0; n < 8; n++) {
                int col = kb*64 + n*8 + 2*kq;
                if (col     > qr_a)     s[n][0] = -1e30f;
                if (col + 1 > qr_a)     s[n][1] = -1e30f;
                if (col     > qr_a + 8) s[n][2] = -1e30f;
                if (col + 1 > qr_a + 8) s[n][3] = -1e30f;
            }
        }

        float mxa = -1e30f, mxb = -1e30f;
        #pragma unroll
        for (int n = 0; n < 8; n++) {
            mxa = fmaxf(mxa, fmaxf(s[n][0], s[n][1]));
            mxb = fmaxf(mxb, fmaxf(s[n][2], s[n][3]));
        }
        mxa = fmaxf(mxa, __shfl_xor_sync(0xffffffffu, mxa, 1));
        mxa = fmaxf(mxa, __shfl_xor_sync(0xffffffffu, mxa, 2));
        mxb = fmaxf(mxb, __shfl_xor_sync(0xffffffffu, mxb, 1));
        mxb = fmaxf(mxb, __shfl_xor_sync(0xffffffffu, mxb, 2));

        float mna = fmaxf(m_a, mxa), mnb = fmaxf(m_b, mxb);
        float alpha_a = __expf(m_a - mna), alpha_b = __expf(m_b - mnb);
        float suma = 0.f, sumb = 0.f;
        #pragma unroll
        for (int n = 0; n < 8; n++) {
            float p0 = __expf(s[n][0] - mna), p1 = __expf(s[n][1] - mna);
            float p2 = __expf(s[n][2] - mnb), p3 = __expf(s[n][3] - mnb);
            suma += p0 + p1; sumb += p2 + p3;
            uint32_t* pp = Ps + (m0 + ra)*PS_S + n*8 + 2*kq;
            pp[0] = f2tf32(p0); pp[1] = f2tf32(p1);
            pp[8*PS_S] = f2tf32(p2); pp[8*PS_S + 1] = f2tf32(p3);
        }
        suma += __shfl_xor_sync(0xffffffffu, suma, 1);
        suma += __shfl_xor_sync(0xffffffffu, suma, 2);
        sumb += __shfl_xor_sync(0xffffffffu, sumb, 1);
        sumb += __shfl_xor_sync(0xffffffffu, sumb, 2);
        l_a = l_a * alpha_a + suma;
        l_b = l_b * alpha_b + sumb;
        m_a = mna; m_b = mnb;
        #pragma unroll
        for (int ni = 0; ni < 16; ni++) {
            o[ni][0] *= alpha_a; o[ni][1] *= alpha_a;
            o[ni][2] *= alpha_b; o[ni][3] *= alpha_b;
        }
        __syncwarp();

        // ---- O += P @ V ----
        #pragma unroll
        for (int k0 = 0; k0 < 64; k0 += 8) {
            uint32_t a[4];
            const uint32_t* pp = Ps + (m0 + ra)*PS_S + k0 + kq;
            a[0] = pp[0]; a[1] = pp[8*PS_S]; a[2] = pp[4]; a[3] = pp[8*PS_S + 4];
            #pragma unroll
            for (int ni = 0; ni < 16; ni++) {
                const uint32_t* vp = Vb + (k0 + kq)*VS_S + ni*8 + ra;
                mma_tf32(o[ni], a, vp[0], vp[4*VS_S]);
            }
        }

        __syncthreads();
        if (kb + 2 < nkb) load_tile(kb + 2);
        else              cp_commit();
    }

    float inva = 1.f / l_a, invb = 1.f / l_b;
    #pragma unroll
    for (int ni = 0; ni < 16; ni++) {
        int cc = h*HD + ni*8 + 2*kq;
        int r  = qb*128 + m0 + ra;
        uint2 v0 = make_uint2(f2tf32(o[ni][0]*inva), f2tf32(o[ni][1]*inva));
        uint2 v1 = make_uint2(f2tf32(o[ni][2]*invb), f2tf32(o[ni][3]*invb));
        *(uint2*)(z + (size_t)r * MODEL + cc)       = v0;
        *(uint2*)(z + (size_t)(r + 8) * MODEL + cc) = v1;
    }
}

// ---------------------------------------------------------------------------
extern "C" void kernel_launch(void* const* d_in, const int* in_sizes, int n_in,
                              void* d_out, int out_size)
{
    const float* x      = (const float*)d_in[0];
    const float* w_attn = (const float*)d_in[1];
    const float* b_attn = (const float*)d_in[2];
    const float* w_proj = (const float*)d_in[3];
    const float* b_proj = (const float*)d_in[4];
    float* out = (float*)d_out;

    float *hid, *z, *xr, *wa, *wp;
    cudaGetSymbolAddress((void**)&hid, g_hidden);
    cudaGetSymbolAddress((void**)&z,   g_z);
    cudaGetSymbolAddress((void**)&xr,  g_xr);
    cudaGetSymbolAddress((void**)&wa,  g_wa);
    cudaGetSymbolAddress((void**)&wp,  g_wp);

    cudaFuncSetAttribute(gemm_tf32<true>,
                         cudaFuncAttributeMaxDynamicSharedMemorySize, GEMM_SMEM);
    cudaFuncSetAttribute(gemm_tf32<false>,
                         cudaFuncAttributeMaxDynamicSharedMemorySize, GEMM_SMEM);
    cudaFuncSetAttribute(flash_tf32,
                         cudaFuncAttributeMaxDynamicSharedMemorySize, FL_SMEM);

    // 0) pre-round GEMM operands (numerics-identical to per-load cvt)
    round_tf32_kernel<<<2048, 256>>>(x,      xr, SEQ*MODEL);
    round_tf32_kernel<<<2048, 256>>>(w_attn, wa, MODEL*QKV_N);
    round_tf32_kernel<<<2048, 256>>>(w_proj, wp, MODEL*MODEL);

    // 1) QKV projection (rounded output feeds flash cvt-free)
    gemm_tf32<true><<<dim3(QKV_N/128, SEQ/128), 256, GEMM_SMEM>>>(
        xr, wa, b_attn, hid, SEQ, QKV_N, MODEL);

    // 2) causal multi-head attention (writes rounded z)
    flash_tf32<<<dim3(SEQ/128, NH), 256, FL_SMEM>>>(hid, z);

    // 3) output projection (fp32 output)
    gemm_tf32<false><<<dim3(MODEL/128, SEQ/128), 256, GEMM_SMEM>>>(
        z, wp, b_proj, out, SEQ, MODEL, MODEL);
}

// round 12
// speedup vs baseline: 2.7285x; 1.7069x over previous
#include <cuda_runtime.h>
#include <cuda_fp16.h>
#include <math.h>
#include <stdint.h>

#define SEQ   4096
#define MODEL 2048
#define NH    16
#define HD    128
#define QKV_N (3*MODEL)

// Scratch (__device__ globals: allocation-free rule)
__device__ __half g_hidden[(size_t)SEQ * QKV_N];   // fp16 QKV output
__device__ __half g_z[(size_t)SEQ * MODEL];        // fp16 attn output
__device__ __half g_xh[(size_t)SEQ * MODEL];       // fp16 x         [SEQ][MODEL]
__device__ __half g_wa[(size_t)MODEL * QKV_N];     // fp16 w_attn^T  [QKV_N][MODEL]
__device__ __half g_wp[(size_t)MODEL * MODEL];     // fp16 w_proj^T  [MODEL][MODEL]

__device__ __forceinline__ uint32_t pack_h2(float a, float b) {
    __half2 h = __floats2half2_rn(a, b);
    return reinterpret_cast<uint32_t&>(h);
}
__device__ __forceinline__ void mma_f16(float* c, const uint32_t* a,
                                        uint32_t b0, uint32_t b1) {
    asm volatile(
        "mma.sync.aligned.m16n8k16.row.col.f32.f16.f16.f32 "
        "{%0,%1,%2,%3}, {%4,%5,%6,%7}, {%8,%9}, {%0,%1,%2,%3};\n"
        : "+f"(c[0]), "+f"(c[1]), "+f"(c[2]), "+f"(c[3])
        : "r"(a[0]), "r"(a[1]), "r"(a[2]), "r"(a[3]), "r"(b0), "r"(b1));
}
__device__ __forceinline__ void ldsm4_t(uint32_t* r, uint32_t addr) {
    asm volatile("ldmatrix.sync.aligned.m8n8.x4.trans.shared.b16 {%0,%1,%2,%3}, [%4];"
        : "=r"(r[0]), "=r"(r[1]), "=r"(r[2]), "=r"(r[3]) : "r"(addr));
}
__device__ __forceinline__ void cp16(uint32_t dst, const void* src) {
    asm volatile("cp.async.cg.shared.global [%0], [%1], 16;\n" :: "r"(dst), "l"(src));
}
__device__ __forceinline__ void cp_commit() { asm volatile("cp.async.commit_group;\n"); }
template<int N> __device__ __forceinline__ void cp_wait() {
    asm volatile("cp.async.wait_group %0;\n" :: "n"(N));
}
__device__ __forceinline__ uint32_t smem_u32(const void* p) {
    uint32_t a;
    asm("{ .reg .u64 t; cvta.to.shared.u64 t, %1; cvt.u32.u64 %0, t; }"
        : "=r"(a) : "l"(p));
    return a;
}

// ---------------------------------------------------------------------------
// Prep kernels
// ---------------------------------------------------------------------------
__global__ void round_half_kernel(const float* __restrict__ in,
                                  uint32_t* __restrict__ out, int n2) {
    int i = blockIdx.x * blockDim.x + threadIdx.x;
    int stride = gridDim.x * blockDim.x;
    for (; i < n2; i += stride) {
        float2 v = *(const float2*)(in + 2*i);
        out[i] = pack_h2(v.x, v.y);
    }
}

// out[c][r] = half(in[r][c]); in [R][C] fp32, out [C][R] fp16 (u32 = 2 r's)
__global__ void transpose_half(const float* __restrict__ in,
                               uint32_t* __restrict__ out, int R, int C) {
    __shared__ float tile[32][33];
    int c0 = blockIdx.x * 32, r0 = blockIdx.y * 32;
    int tx = threadIdx.x, ty = threadIdx.y;
    #pragma unroll
    for (int i = 0; i < 32; i += 8)
        tile[ty + i][tx] = in[(size_t)(r0 + ty + i) * C + c0 + tx];
    __syncthreads();
    if (tx < 16) {
        #pragma unroll
        for (int i = 0; i < 32; i += 8) {
            int cc = ty + i;
            out[(size_t)(c0 + cc) * (R/2) + r0/2 + tx] =
                pack_h2(tile[2*tx][cc], tile[2*tx + 1][cc]);
        }
    }
}

// ---------------------------------------------------------------------------
// fp16 GEMM: C[M,N] = A[M,K] @ Bt[N,K]^T + bias. A,Bt fp16, fp32 accum.
// 128x128 tile, BK=32 (2 k16 steps), 256 thr (2x4 warps, 64x32 warp tile),
// cp.async 4-stage, scalar half2 fragment LDS, 2 CTAs/SM.
// ---------------------------------------------------------------------------
#define GS 4
#define RST 20                           // u32/row: 16 data + 4 pad
#define TILE_U32 (128*RST)
#define STAGE_U32 (2*TILE_U32)
#define GEMM_SMEM (GS*STAGE_U32*4)       // 80 KB

template<bool OUT_HALF>
__global__ __launch_bounds__(256, 2) void gemm_f16(
    const __half* __restrict__ A, const __half* __restrict__ Bt,
    const float* __restrict__ bias, void* __restrict__ Cv,
    int M, int N, int K)
{
    extern __shared__ uint32_t gsm[];
    const uint32_t* Ah = (const uint32_t*)A;
    const uint32_t* Bh = (const uint32_t*)Bt;
    const int Kw = K >> 1;               // u32 per row

    const int tid  = threadIdx.x;
    const int lane = tid & 31;
    const int warp = tid >> 5;
    const int ra   = lane >> 2;
    const int kq   = lane & 3;
    const int m0 = (warp >> 2) * 64;
    const int n0 = (warp & 3) * 32;
    const int row0 = blockIdx.y * 128, col0 = blockIdx.x * 128;

    const int ldr = tid >> 1;            // loader row 0..127
    const int ldc = (tid & 1) * 2;       // chunks {0,1} or {2,3}

    uint32_t asS = (uint32_t)__cvta_generic_to_shared(gsm);
    const int niter = K >> 5;

    auto issue = [&](int t) {
        uint32_t sb = asS + (uint32_t)(t & (GS-1)) * STAGE_U32 * 4u;
        const uint32_t* ap = Ah + (size_t)(row0 + ldr) * Kw + t*16;
        uint32_t ad = sb + (uint32_t)(ldr * RST) * 4u;
        cp16(ad + ldc*16u,     ap + ldc*4);
        cp16(ad + (ldc+1)*16u, ap + (ldc+1)*4);
        const uint32_t* bp = Bh + (size_t)(col0 + ldr) * Kw + t*16;
        uint32_t bd = sb + (uint32_t)TILE_U32*4u + (uint32_t)(ldr * RST) * 4u;
        cp16(bd + ldc*16u,     bp + ldc*4);
        cp16(bd + (ldc+1)*16u, bp + (ldc+1)*4);
        cp_commit();
    };

    #pragma unroll
    for (int s = 0; s < GS - 1; s++) issue(s);

    float c[4][4][4];
    #pragma unroll
    for (int mi = 0; mi < 4; mi++)
        #pragma unroll
        for (int ni = 0; ni < 4; ni++)
            #pragma unroll
            for (int r = 0; r < 4; r++) c[mi][ni][r] = 0.f;

    for (int i = 0; i < niter; i++) {
        cp_wait<GS-2>();
        __syncthreads();
        if (i + GS - 1 < niter) issue(i + GS - 1);
        else                    cp_commit();

        const uint32_t* Ab = gsm + (size_t)(i & (GS-1)) * STAGE_U32;
        const uint32_t* Bb = Ab + TILE_U32;

        #pragma unroll
        for (int kk = 0; kk < 2; kk++) {
            uint32_t af[4][4];
            #pragma unroll
            for (int mi = 0; mi < 4; mi++) {
                const uint32_t* p = Ab + (m0 + mi*16 + ra)*RST + kk*8 + kq;
                af[mi][0] = p[0];
                af[mi][1] = p[8*RST];
                af[mi][2] = p[4];
                af[mi][3] = p[8*RST + 4];
            }
            #pragma unroll
            for (int ni = 0; ni < 4; ni++) {
                const uint32_t* bp = Bb + (n0 + ni*8 + ra)*RST + kk*8 + kq;
                uint32_t b0 = bp[0];
                uint32_t b1 = bp[4];
                #pragma unroll
                for (int mi = 0; mi < 4; mi++)
                    mma_f16(c[mi][ni], af[mi], b0, b1);
            }
        }
    }

    #pragma unroll
    for (int ni = 0; ni < 4; ni++) {
        int cc = col0 + n0 + ni*8 + 2*kq;
        float2 bb = *(const float2*)(bias + cc);
        #pragma unroll
        for (int mi = 0; mi < 4; mi++) {
            int r = row0 + m0 + mi*16 + ra;
            float o0 = c[mi][ni][0] + bb.x, o1 = c[mi][ni][1] + bb.y;
            float o2 = c[mi][ni][2] + bb.x, o3 = c[mi][ni][3] + bb.y;
            if (OUT_HALF) {
                uint32_t* C32 = (uint32_t*)Cv;
                C32[(size_t)r * (N>>1) + (cc>>1)]       = pack_h2(o0, o1);
                C32[(size_t)(r + 8) * (N>>1) + (cc>>1)] = pack_h2(o2, o3);
            } else {
                float* C = (float*)Cv;
                *(float2*)(C + (size_t)r * N + cc)       = make_float2(o0, o1);
                *(float2*)(C + (size_t)(r + 8) * N + cc) = make_float2(o2, o3);
            }
        }
    }
}

// ---------------------------------------------------------------------------
// fp16 flash attention (causal). Q block 128 (fragments in registers),
// key tile 64, K/V double-buffered cp.async. 8 warps x 16 q-rows.
// S: Q(reg) x K(smem, natural layout). PV: P(smem half2) x V via ldmatrix.trans.
// ---------------------------------------------------------------------------
#define KS 68                            // u32/row: 64 data + 4 pad
#define VS 68
#define PS 36                            // u32/row: 32 data + 4 pad
#define FL_SMEM ((2*64*KS + 2*64*VS + 128*PS)*4)   // 88 KB

__global__ __launch_bounds__(256, 1) void flash_f16(
    const __half* __restrict__ hidden, __half* __restrict__ z)
{
    extern __shared__ uint32_t sm[];
    uint32_t* Ks = sm;                    // [2][64][KS]
    uint32_t* Vs = Ks + 2*64*KS;          // [2][64][VS]
    uint32_t* Ps = Vs + 2*64*VS;          // [128][PS]

    const uint32_t* hid32 = (const uint32_t*)hidden;
    const int Qw = QKV_N >> 1;            // u32 per hidden row

    const int h    = blockIdx.y;
    const int qb   = (int)(gridDim.x - 1) - (int)blockIdx.x;  // heavy first
    const int tid  = threadIdx.x;
    const int lane = tid & 31;
    const int warp = tid >> 5;
    const int m0   = warp * 16;
    const int ra   = lane >> 2;
    const int kq   = lane & 3;
    const float scale = 0.08838834764831845f;  // 1/sqrt(128)

    uint32_t asK = smem_u32(Ks);
    uint32_t asV = smem_u32(Vs);
    const int hoff = (MODEL >> 1) + (h*HD >> 1);  // K base u32 within row

    auto load_tile = [&](int t) {
        uint32_t kb_ = asK + (uint32_t)(t & 1) * 64u*KS*4u;
        uint32_t vb_ = asV + (uint32_t)(t & 1) * 64u*VS*4u;
        #pragma unroll
        for (int i = 0; i < 4; i++) {
            int idx = tid + 256*i;
            int r = idx >> 4, c = idx & 15;
            const uint32_t* kp = hid32 + (size_t)(t*64 + r) * Qw + hoff + c*4;
            cp16(kb_ + (uint32_t)(r*KS + c*4)*4u, kp);
            cp16(vb_ + (uint32_t)(r*VS + c*4)*4u, kp + (MODEL >> 1));
        }
        cp_commit();
    };

    // Q fragments straight to registers (fp16)
    uint32_t qf[8][4];
    {
        const uint32_t* qp0 = hid32 + (size_t)(qb*128 + m0 + ra) * Qw + (h*HD >> 1);
        const uint32_t* qp1 = qp0 + (size_t)8 * Qw;
        #pragma unroll
        for (int i = 0; i < 8; i++) {
            qf[i][0] = qp0[i*8 + kq];
            qf[i][1] = qp1[i*8 + kq];
            qf[i][2] = qp0[i*8 + kq + 4];
            qf[i][3] = qp1[i*8 + kq + 4];
        }
    }

    float m_a = -1e30f, m_b = -1e30f, l_a = 0.f, l_b = 0.f;
    float o[16][4];
    #pragma unroll
    for (int ni = 0; ni < 16; ni++)
        o[ni][0] = o[ni][1] = o[ni][2] = o[ni][3] = 0.f;

    const int qr_a = qb*128 + m0 + ra;
    const int nkb  = 2*qb + 2;

    load_tile(0);
    load_tile(1);

    for (int kb = 0; kb < nkb; kb++) {
        cp_wait<1>();
        __syncthreads();

        const uint32_t* Kb = Ks + (kb & 1)*64*KS;
        uint32_t vb_byte = asV + (uint32_t)(kb & 1)*64u*VS*4u;

        // ---- S = Q @ K^T ----
        float s[8][4];
        #pragma unroll
        for (int n = 0; n < 8; n++) s[n][0] = s[n][1] = s[n][2] = s[n][3] = 0.f;

        #pragma unroll
        for (int i = 0; i < 8; i++) {
            #pragma unroll
            for (int n = 0; n < 8; n++) {
                const uint32_t* kp2 = Kb + (n*8 + ra)*KS + i*8 + kq;
                mma_f16(s[n], qf[i], kp2[0], kp2[4]);
            }
        }

        #pragma unroll
        for (int n = 0; n < 8; n++) {
            s[n][0] *= scale; s[n][1] *= scale;
            s[n][2] *= scale; s[n][3] *= scale;
        }

        // ---- causal mask (near-diagonal tiles only) ----
        if (kb >= 2*qb) {
            #pragma unroll
            for (int n = 0; n < 8; n++) {
                int col = kb*64 + n*8 + 2*kq;
                if (col     > qr_a)     s[n][0] = -1e30f;
                if (col + 1 > qr_a)     s[n][1] = -1e30f;
                if (col     > qr_a + 8) s[n][2] = -1e30f;
                if (col + 1 > qr_a + 8) s[n][3] = -1e30f;
            }
        }

        // ---- online softmax ----
        float mxa = -1e30f, mxb = -1e30f;
        #pragma unroll
        for (int n = 0; n < 8; n++) {
            mxa = fmaxf(mxa, fmaxf(s[n][0], s[n][1]));
            mxb = fmaxf(mxb, fmaxf(s[n][2], s[n][3]));
        }
        mxa = fmaxf(mxa, __shfl_xor_sync(0xffffffffu, mxa, 1));
        mxa = fmaxf(mxa, __shfl_xor_sync(0xffffffffu, mxa, 2));
        mxb = fmaxf(mxb, __shfl_xor_sync(0xffffffffu, mxb, 1));
        mxb = fmaxf(mxb, __shfl_xor_sync(0xffffffffu, mxb, 2));

        float mna = fmaxf(m_a, mxa), mnb = fmaxf(m_b, mxb);
        float alpha_a = __expf(m_a - mna), alpha_b = __expf(m_b - mnb);
        float suma = 0.f, sumb = 0.f;
        #pragma unroll
        for (int n = 0; n < 8; n++) {
            float p0 = __expf(s[n][0] - mna), p1 = __expf(s[n][1] - mna);
            float p2 = __expf(s[n][2] - mnb), p3 = __expf(s[n][3] - mnb);
            suma += p0 + p1; sumb += p2 + p3;
            Ps[(m0 + ra)*PS + n*4 + kq]     = pack_h2(p0, p1);
            Ps[(m0 + ra + 8)*PS + n*4 + kq] = pack_h2(p2, p3);
        }
        suma += __shfl_xor_sync(0xffffffffu, suma, 1);
        suma += __shfl_xor_sync(0xffffffffu, suma, 2);
        sumb += __shfl_xor_sync(0xffffffffu, sumb, 1);
        sumb += __shfl_xor_sync(0xffffffffu, sumb, 2);
        l_a = l_a * alpha_a + suma;
        l_b = l_b * alpha_b + sumb;
        m_a = mna; m_b = mnb;
        #pragma unroll
        for (int ni = 0; ni < 16; ni++) {
            o[ni][0] *= alpha_a; o[ni][1] *= alpha_a;
            o[ni][2] *= alpha_b; o[ni][3] *= alpha_b;
        }
        __syncwarp();

        // ---- O += P @ V  (V B-frags via ldmatrix.trans) ----
        const int g  = lane >> 3;            // tile index 0..3
        const int rr = lane & 7;             // row within tile
        #pragma unroll
        for (int s4 = 0; s4 < 4; s4++) {     // k16 steps over K=64
            uint32_t a[4];
            const uint32_t* pp = Ps + (m0 + ra)*PS + s4*8 + kq;
            a[0] = pp[0];
            a[1] = pp[8*PS];
            a[2] = pp[4];
            a[3] = pp[8*PS + 4];
            #pragma unroll
            for (int nn = 0; nn < 8; nn++) { // pairs of n8 groups (d=16 each)
                uint32_t bf[4];
                uint32_t addr = vb_byte +
                    (uint32_t)((s4*16 + (g & 1)*8 + rr)*VS + nn*8 + (g >> 1)*4) * 4u;
                ldsm4_t(bf, addr);
                mma_f16(o[2*nn],     a, bf[0], bf[1]);
                mma_f16(o[2*nn + 1], a, bf[2], bf[3]);
            }
        }

        __syncthreads();
        if (kb + 2 < nkb) load_tile(kb + 2);
        else              cp_commit();
    }

    // ---- normalize + write z (fp16) ----
    float inva = 1.f / l_a, invb = 1.f / l_b;
    uint32_t* z32 = (uint32_t*)z;
    #pragma unroll
    for (int ni = 0; ni < 16; ni++) {
        int cw = h*(HD >> 1) + ni*4 + kq;
        int r  = qb*128 + m0 + ra;
        z32[(size_t)r * (MODEL >> 1) + cw]       = pack_h2(o[ni][0]*inva, o[ni][1]*inva);
        z32[(size_t)(r + 8) * (MODEL >> 1) + cw] = pack_h2(o[ni][2]*invb, o[ni][3]*invb);
    }
}

// ---------------------------------------------------------------------------
extern "C" void kernel_launch(void* const* d_in, const int* in_sizes, int n_in,
                              void* d_out, int out_size)
{
    const float* x      = (const float*)d_in[0];
    const float* w_attn = (const float*)d_in[1];
    const float* b_attn = (const float*)d_in[2];
    const float* w_proj = (const float*)d_in[3];
    const float* b_proj = (const float*)d_in[4];
    float* out = (float*)d_out;

    __half *hid, *z, *xh, *wa, *wp;
    cudaGetSymbolAddress((void**)&hid, g_hidden);
    cudaGetSymbolAddress((void**)&z,   g_z);
    cudaGetSymbolAddress((void**)&xh,  g_xh);
    cudaGetSymbolAddress((void**)&wa,  g_wa);
    cudaGetSymbolAddress((void**)&wp,  g_wp);

    cudaFuncSetAttribute(gemm_f16<true>,
                         cudaFuncAttributeMaxDynamicSharedMemorySize, GEMM_SMEM);
    cudaFuncSetAttribute(gemm_f16<false>,
                         cudaFuncAttributeMaxDynamicSharedMemorySize, GEMM_SMEM);
    cudaFuncSetAttribute(flash_f16,
                         cudaFuncAttributeMaxDynamicSharedMemorySize, FL_SMEM);

    // 0) prep: x -> fp16; weights -> fp16 transposed [N][K]
    round_half_kernel<<<2048, 256>>>(x, (uint32_t*)xh, SEQ*MODEL/2);
    transpose_half<<<dim3(QKV_N/32, MODEL/32), dim3(32, 8)>>>(
        w_attn, (uint32_t*)wa, MODEL, QKV_N);
    transpose_half<<<dim3(MODEL/32, MODEL/32), dim3(32, 8)>>>(
        w_proj, (uint32_t*)wp, MODEL, MODEL);

    // 1) QKV projection (fp16 out feeds flash directly)
    gemm_f16<true><<<dim3(QKV_N/128, SEQ/128), 256, GEMM_SMEM>>>(
        xh, wa, b_attn, hid, SEQ, QKV_N, MODEL);

    // 2) causal multi-head attention (fp16 z)
    flash_f16<<<dim3(SEQ/128, NH), 256, FL_SMEM>>>(hid, z);

    // 3) output projection (fp32 out)
    gemm_f16<false><<<dim3(MODEL/128, SEQ/128), 256, GEMM_SMEM>>>(
        z, wp, b_proj, out, SEQ, MODEL, MODEL);
}

// round 13
// speedup vs baseline: 2.9227x; 1.0712x over previous
#include <cuda_runtime.h>
#include <cuda_fp16.h>
#include <math.h>
#include <stdint.h>

#define SEQ   4096
#define MODEL 2048
#define NH    16
#define HD    128
#define QKV_N (3*MODEL)

// Scratch (__device__ globals: allocation-free rule)
__device__ __half g_hidden[(size_t)SEQ * QKV_N];   // fp16 QKV output
__device__ __half g_z[(size_t)SEQ * MODEL];        // fp16 attn output
__device__ __half g_xh[(size_t)SEQ * MODEL];       // fp16 x         [SEQ][MODEL]
__device__ __half g_wa[(size_t)MODEL * QKV_N];     // fp16 w_attn^T  [QKV_N][MODEL]
__device__ __half g_wp[(size_t)MODEL * MODEL];     // fp16 w_proj^T  [MODEL][MODEL]

__device__ __forceinline__ uint32_t pack_h2(float a, float b) {
    __half2 h = __floats2half2_rn(a, b);
    return reinterpret_cast<uint32_t&>(h);
}
__device__ __forceinline__ void mma_f16(float* c, const uint32_t* a,
                                        uint32_t b0, uint32_t b1) {
    asm volatile(
        "mma.sync.aligned.m16n8k16.row.col.f32.f16.f16.f32 "
        "{%0,%1,%2,%3}, {%4,%5,%6,%7}, {%8,%9}, {%0,%1,%2,%3};\n"
        : "+f"(c[0]), "+f"(c[1]), "+f"(c[2]), "+f"(c[3])
        : "r"(a[0]), "r"(a[1]), "r"(a[2]), "r"(a[3]), "r"(b0), "r"(b1));
}
__device__ __forceinline__ void ldsm4_t(uint32_t* r, uint32_t addr) {
    asm volatile("ldmatrix.sync.aligned.m8n8.x4.trans.shared.b16 {%0,%1,%2,%3}, [%4];"
        : "=r"(r[0]), "=r"(r[1]), "=r"(r[2]), "=r"(r[3]) : "r"(addr));
}
__device__ __forceinline__ void cp16(uint32_t dst, const void* src) {
    asm volatile("cp.async.cg.shared.global [%0], [%1], 16;\n" :: "r"(dst), "l"(src));
}
__device__ __forceinline__ void cp_commit() { asm volatile("cp.async.commit_group;\n"); }
template<int N> __device__ __forceinline__ void cp_wait() {
    asm volatile("cp.async.wait_group %0;\n" :: "n"(N));
}
__device__ __forceinline__ uint32_t smem_u32(const void* p) {
    uint32_t a;
    asm("{ .reg .u64 t; cvta.to.shared.u64 t, %1; cvt.u32.u64 %0, t; }"
        : "=r"(a) : "l"(p));
    return a;
}

// ---------------------------------------------------------------------------
// Prep kernels
// ---------------------------------------------------------------------------
__global__ void round_half_kernel(const float* __restrict__ in,
                                  uint32_t* __restrict__ out, int n2) {
    int i = blockIdx.x * blockDim.x + threadIdx.x;
    int stride = gridDim.x * blockDim.x;
    for (; i < n2; i += stride) {
        float2 v = *(const float2*)(in + 2*i);
        out[i] = pack_h2(v.x, v.y);
    }
}

// out[c][r] = half(in[r][c]); in [R][C] fp32, out [C][R] fp16 (u32 = 2 r's)
__global__ void transpose_half(const float* __restrict__ in,
                               uint32_t* __restrict__ out, int R, int C) {
    __shared__ float tile[32][33];
    int c0 = blockIdx.x * 32, r0 = blockIdx.y * 32;
    int tx = threadIdx.x, ty = threadIdx.y;
    #pragma unroll
    for (int i = 0; i < 32; i += 8)
        tile[ty + i][tx] = in[(size_t)(r0 + ty + i) * C + c0 + tx];
    __syncthreads();
    if (tx < 16) {
        #pragma unroll
        for (int i = 0; i < 32; i += 8) {
            int cc = ty + i;
            out[(size_t)(c0 + cc) * (R/2) + r0/2 + tx] =
                pack_h2(tile[2*tx][cc], tile[2*tx + 1][cc]);
        }
    }
}

// ---------------------------------------------------------------------------
// fp16 GEMM: C[M,N] = A[M,K] @ Bt[N,K]^T + bias. A,Bt fp16, fp32 accum.
// 128x128 tile, BK=32, 256 thr (2x4 warps, 64x32 warp tile), cp.async 4-stage,
// 2 CTAs/SM. ALL fragments for the iteration loaded up front (48 regs), then
// 32 MMAs back-to-back — LDS latency hidden by the second load stream.
// ---------------------------------------------------------------------------
#define GS 4
#define RST 20                           // u32/row: 16 data + 4 pad
#define TILE_U32 (128*RST)
#define STAGE_U32 (2*TILE_U32)
#define GEMM_SMEM (GS*STAGE_U32*4)       // 80 KB

template<bool OUT_HALF>
__global__ __launch_bounds__(256, 2) void gemm_f16(
    const __half* __restrict__ A, const __half* __restrict__ Bt,
    const float* __restrict__ bias, void* __restrict__ Cv,
    int M, int N, int K)
{
    extern __shared__ uint32_t gsm[];
    const uint32_t* Ah = (const uint32_t*)A;
    const uint32_t* Bh = (const uint32_t*)Bt;
    const int Kw = K >> 1;               // u32 per row

    const int tid  = threadIdx.x;
    const int lane = tid & 31;
    const int warp = tid >> 5;
    const int ra   = lane >> 2;
    const int kq   = lane & 3;
    const int m0 = (warp >> 2) * 64;
    const int n0 = (warp & 3) * 32;
    const int row0 = blockIdx.y * 128, col0 = blockIdx.x * 128;

    const int ldr = tid >> 1;            // loader row 0..127
    const int ldc = (tid & 1) * 2;       // chunks {0,1} or {2,3}

    uint32_t asS = (uint32_t)__cvta_generic_to_shared(gsm);
    const int niter = K >> 5;

    auto issue = [&](int t) {
        uint32_t sb = asS + (uint32_t)(t & (GS-1)) * STAGE_U32 * 4u;
        const uint32_t* ap = Ah + (size_t)(row0 + ldr) * Kw + t*16;
        uint32_t ad = sb + (uint32_t)(ldr * RST) * 4u;
        cp16(ad + ldc*16u,     ap + ldc*4);
        cp16(ad + (ldc+1)*16u, ap + (ldc+1)*4);
        const uint32_t* bp = Bh + (size_t)(col0 + ldr) * Kw + t*16;
        uint32_t bd = sb + (uint32_t)TILE_U32*4u + (uint32_t)(ldr * RST) * 4u;
        cp16(bd + ldc*16u,     bp + ldc*4);
        cp16(bd + (ldc+1)*16u, bp + (ldc+1)*4);
        cp_commit();
    };

    #pragma unroll
    for (int s = 0; s < GS - 1; s++) issue(s);

    float c[4][4][4];
    #pragma unroll
    for (int mi = 0; mi < 4; mi++)
        #pragma unroll
        for (int ni = 0; ni < 4; ni++)
            #pragma unroll
            for (int r = 0; r < 4; r++) c[mi][ni][r] = 0.f;

    for (int i = 0; i < niter; i++) {
        cp_wait<GS-2>();
        __syncthreads();

        const uint32_t* Ab = gsm + (size_t)(i & (GS-1)) * STAGE_U32;
        const uint32_t* Bb = Ab + TILE_U32;

        // ---- load ALL fragments for both k16 steps up front ----
        uint32_t af[2][4][4];
        uint32_t bf[2][4][2];
        #pragma unroll
        for (int kk = 0; kk < 2; kk++) {
            #pragma unroll
            for (int mi = 0; mi < 4; mi++) {
                const uint32_t* p = Ab + (m0 + mi*16 + ra)*RST + kk*8 + kq;
                af[kk][mi][0] = p[0];
                af[kk][mi][1] = p[8*RST];
                af[kk][mi][2] = p[4];
                af[kk][mi][3] = p[8*RST + 4];
            }
            #pragma unroll
            for (int ni = 0; ni < 4; ni++) {
                const uint32_t* bp = Bb + (n0 + ni*8 + ra)*RST + kk*8 + kq;
                bf[kk][ni][0] = bp[0];
                bf[kk][ni][1] = bp[4];
            }
        }

        // next-stage global prefetch (after the critical LDS hit the LSU)
        if (i + GS - 1 < niter) issue(i + GS - 1);
        else                    cp_commit();

        // ---- 32 MMAs back-to-back ----
        #pragma unroll
        for (int kk = 0; kk < 2; kk++)
            #pragma unroll
            for (int ni = 0; ni < 4; ni++)
                #pragma unroll
                for (int mi = 0; mi < 4; mi++)
                    mma_f16(c[mi][ni], af[kk][mi], bf[kk][ni][0], bf[kk][ni][1]);
    }

    #pragma unroll
    for (int ni = 0; ni < 4; ni++) {
        int cc = col0 + n0 + ni*8 + 2*kq;
        float2 bb = *(const float2*)(bias + cc);
        #pragma unroll
        for (int mi = 0; mi < 4; mi++) {
            int r = row0 + m0 + mi*16 + ra;
            float o0 = c[mi][ni][0] + bb.x, o1 = c[mi][ni][1] + bb.y;
            float o2 = c[mi][ni][2] + bb.x, o3 = c[mi][ni][3] + bb.y;
            if (OUT_HALF) {
                uint32_t* C32 = (uint32_t*)Cv;
                C32[(size_t)r * (N>>1) + (cc>>1)]       = pack_h2(o0, o1);
                C32[(size_t)(r + 8) * (N>>1) + (cc>>1)] = pack_h2(o2, o3);
            } else {
                float* C = (float*)Cv;
                *(float2*)(C + (size_t)r * N + cc)       = make_float2(o0, o1);
                *(float2*)(C + (size_t)(r + 8) * N + cc) = make_float2(o2, o3);
            }
        }
    }
}

// ---------------------------------------------------------------------------
// fp16 flash attention (causal) — unchanged from R12.
// ---------------------------------------------------------------------------
#define KS 68                            // u32/row: 64 data + 4 pad
#define VS 68
#define PS 36                            // u32/row: 32 data + 4 pad
#define FL_SMEM ((2*64*KS + 2*64*VS + 128*PS)*4)   // 88 KB

__global__ __launch_bounds__(256, 1) void flash_f16(
    const __half* __restrict__ hidden, __half* __restrict__ z)
{
    extern __shared__ uint32_t sm[];
    uint32_t* Ks = sm;                    // [2][64][KS]
    uint32_t* Vs = Ks + 2*64*KS;          // [2][64][VS]
    uint32_t* Ps = Vs + 2*64*VS;          // [128][PS]

    const uint32_t* hid32 = (const uint32_t*)hidden;
    const int Qw = QKV_N >> 1;            // u32 per hidden row

    const int h    = blockIdx.y;
    const int qb   = (int)(gridDim.x - 1) - (int)blockIdx.x;  // heavy first
    const int tid  = threadIdx.x;
    const int lane = tid & 31;
    const int warp = tid >> 5;
    const int m0   = warp * 16;
    const int ra   = lane >> 2;
    const int kq   = lane & 3;
    const float scale = 0.08838834764831845f;  // 1/sqrt(128)

    uint32_t asK = smem_u32(Ks);
    uint32_t asV = smem_u32(Vs);
    const int hoff = (MODEL >> 1) + (h*HD >> 1);  // K base u32 within row

    auto load_tile = [&](int t) {
        uint32_t kb_ = asK + (uint32_t)(t & 1) * 64u*KS*4u;
        uint32_t vb_ = asV + (uint32_t)(t & 1) * 64u*VS*4u;
        #pragma unroll
        for (int i = 0; i < 4; i++) {
            int idx = tid + 256*i;
            int r = idx >> 4, c = idx & 15;
            const uint32_t* kp = hid32 + (size_t)(t*64 + r) * Qw + hoff + c*4;
            cp16(kb_ + (uint32_t)(r*KS + c*4)*4u, kp);
            cp16(vb_ + (uint32_t)(r*VS + c*4)*4u, kp + (MODEL >> 1));
        }
        cp_commit();
    };

    // Q fragments straight to registers (fp16)
    uint32_t qf[8][4];
    {
        const uint32_t* qp0 = hid32 + (size_t)(qb*128 + m0 + ra) * Qw + (h*HD >> 1);
        const uint32_t* qp1 = qp0 + (size_t)8 * Qw;
        #pragma unroll
        for (int i = 0; i < 8; i++) {
            qf[i][0] = qp0[i*8 + kq];
            qf[i][1] = qp1[i*8 + kq];
            qf[i][2] = qp0[i*8 + kq + 4];
            qf[i][3] = qp1[i*8 + kq + 4];
        }
    }

    float m_a = -1e30f, m_b = -1e30f, l_a = 0.f, l_b = 0.f;
    float o[16][4];
    #pragma unroll
    for (int ni = 0; ni < 16; ni++)
        o[ni][0] = o[ni][1] = o[ni][2] = o[ni][3] = 0.f;

    const int qr_a = qb*128 + m0 + ra;
    const int nkb  = 2*qb + 2;

    load_tile(0);
    load_tile(1);

    for (int kb = 0; kb < nkb; kb++) {
        cp_wait<1>();
        __syncthreads();

        const uint32_t* Kb = Ks + (kb & 1)*64*KS;
        uint32_t vb_byte = asV + (uint32_t)(kb & 1)*64u*VS*4u;

        // ---- S = Q @ K^T ----
        float s[8][4];
        #pragma unroll
        for (int n = 0; n < 8; n++) s[n][0] = s[n][1] = s[n][2] = s[n][3] = 0.f;

        #pragma unroll
        for (int i = 0; i < 8; i++) {
            #pragma unroll
            for (int n = 0; n < 8; n++) {
                const uint32_t* kp2 = Kb + (n*8 + ra)*KS + i*8 + kq;
                mma_f16(s[n], qf[i], kp2[0], kp2[4]);
            }
        }

        #pragma unroll
        for (int n = 0; n < 8; n++) {
            s[n][0] *= scale; s[n][1] *= scale;
            s[n][2] *= scale; s[n][3] *= scale;
        }

        // ---- causal mask (near-diagonal tiles only) ----
        if (kb >= 2*qb) {
            #pragma unroll
            for (int n = 0; n < 8; n++) {
                int col = kb*64 + n*8 + 2*kq;
                if (col     > qr_a)     s[n][0] = -1e30f;
                if (col + 1 > qr_a)     s[n][1] = -1e30f;
                if (col     > qr_a + 8) s[n][2] = -1e30f;
                if (col + 1 > qr_a + 8) s[n][3] = -1e30f;
            }
        }

        // ---- online softmax ----
        float mxa = -1e30f, mxb = -1e30f;
        #pragma unroll
        for (int n = 0; n < 8; n++) {
            mxa = fmaxf(mxa, fmaxf(s[n][0], s[n][1]));
            mxb = fmaxf(mxb, fmaxf(s[n][2], s[n][3]));
        }
        mxa = fmaxf(mxa, __shfl_xor_sync(0xffffffffu, mxa, 1));
        mxa = fmaxf(mxa, __shfl_xor_sync(0xffffffffu, mxa, 2));
        mxb = fmaxf(mxb, __shfl_xor_sync(0xffffffffu, mxb, 1));
        mxb = fmaxf(mxb, __shfl_xor_sync(0xffffffffu, mxb, 2));

        float mna = fmaxf(m_a, mxa), mnb = fmaxf(m_b, mxb);
        float alpha_a = __expf(m_a - mna), alpha_b = __expf(m_b - mnb);
        float suma = 0.f, sumb = 0.f;
        #pragma unroll
        for (int n = 0; n < 8; n++) {
            float p0 = __expf(s[n][0] - mna), p1 = __expf(s[n][1] - mna);
            float p2 = __expf(s[n][2] - mnb), p3 = __expf(s[n][3] - mnb);
            suma += p0 + p1; sumb += p2 + p3;
            Ps[(m0 + ra)*PS + n*4 + kq]     = pack_h2(p0, p1);
            Ps[(m0 + ra + 8)*PS + n*4 + kq] = pack_h2(p2, p3);
        }
        suma += __shfl_xor_sync(0xffffffffu, suma, 1);
        suma += __shfl_xor_sync(0xffffffffu, suma, 2);
        sumb += __shfl_xor_sync(0xffffffffu, sumb, 1);
        sumb += __shfl_xor_sync(0xffffffffu, sumb, 2);
        l_a = l_a * alpha_a + suma;
        l_b = l_b * alpha_b + sumb;
        m_a = mna; m_b = mnb;
        #pragma unroll
        for (int ni = 0; ni < 16; ni++) {
            o[ni][0] *= alpha_a; o[ni][1] *= alpha_a;
            o[ni][2] *= alpha_b; o[ni][3] *= alpha_b;
        }
        __syncwarp();

        // ---- O += P @ V  (V B-frags via ldmatrix.trans) ----
        const int g  = lane >> 3;            // tile index 0..3
        const int rr = lane & 7;             // row within tile
        #pragma unroll
        for (int s4 = 0; s4 < 4; s4++) {     // k16 steps over K=64
            uint32_t a[4];
            const uint32_t* pp = Ps + (m0 + ra)*PS + s4*8 + kq;
            a[0] = pp[0];
            a[1] = pp[8*PS];
            a[2] = pp[4];
            a[3] = pp[8*PS + 4];
            #pragma unroll
            for (int nn = 0; nn < 8; nn++) { // pairs of n8 groups (d=16 each)
                uint32_t bf[4];
                uint32_t addr = vb_byte +
                    (uint32_t)((s4*16 + (g & 1)*8 + rr)*VS + nn*8 + (g >> 1)*4) * 4u;
                ldsm4_t(bf, addr);
                mma_f16(o[2*nn],     a, bf[0], bf[1]);
                mma_f16(o[2*nn + 1], a, bf[2], bf[3]);
            }
        }

        __syncthreads();
        if (kb + 2 < nkb) load_tile(kb + 2);
        else              cp_commit();
    }

    // ---- normalize + write z (fp16) ----
    float inva = 1.f / l_a, invb = 1.f / l_b;
    uint32_t* z32 = (uint32_t*)z;
    #pragma unroll
    for (int ni = 0; ni < 16; ni++) {
        int cw = h*(HD >> 1) + ni*4 + kq;
        int r  = qb*128 + m0 + ra;
        z32[(size_t)r * (MODEL >> 1) + cw]       = pack_h2(o[ni][0]*inva, o[ni][1]*inva);
        z32[(size_t)(r + 8) * (MODEL >> 1) + cw] = pack_h2(o[ni][2]*invb, o[ni][3]*invb);
    }
}

// ---------------------------------------------------------------------------
extern "C" void kernel_launch(void* const* d_in, const int* in_sizes, int n_in,
                              void* d_out, int out_size)
{
    const float* x      = (const float*)d_in[0];
    const float* w_attn = (const float*)d_in[1];
    const float* b_attn = (const float*)d_in[2];
    const float* w_proj = (const float*)d_in[3];
    const float* b_proj = (const float*)d_in[4];
    float* out = (float*)d_out;

    __half *hid, *z, *xh, *wa, *wp;
    cudaGetSymbolAddress((void**)&hid, g_hidden);
    cudaGetSymbolAddress((void**)&z,   g_z);
    cudaGetSymbolAddress((void**)&xh,  g_xh);
    cudaGetSymbolAddress((void**)&wa,  g_wa);
    cudaGetSymbolAddress((void**)&wp,  g_wp);

    cudaFuncSetAttribute(gemm_f16<true>,
                         cudaFuncAttributeMaxDynamicSharedMemorySize, GEMM_SMEM);
    cudaFuncSetAttribute(gemm_f16<false>,
                         cudaFuncAttributeMaxDynamicSharedMemorySize, GEMM_SMEM);
    cudaFuncSetAttribute(flash_f16,
                         cudaFuncAttributeMaxDynamicSharedMemorySize, FL_SMEM);

    // 0) prep: x -> fp16; weights -> fp16 transposed [N][K]
    round_half_kernel<<<2048, 256>>>(x, (uint32_t*)xh, SEQ*MODEL/2);
    transpose_half<<<dim3(QKV_N/32, MODEL/32), dim3(32, 8)>>>(
        w_attn, (uint32_t*)wa, MODEL, QKV_N);
    transpose_half<<<dim3(MODEL/32, MODEL/32), dim3(32, 8)>>>(
        w_proj, (uint32_t*)wp, MODEL, MODEL);

    // 1) QKV projection (fp16 out feeds flash directly)
    gemm_f16<true><<<dim3(QKV_N/128, SEQ/128), 256, GEMM_SMEM>>>(
        xh, wa, b_attn, hid, SEQ, QKV_N, MODEL);

    // 2) causal multi-head attention (fp16 z)
    flash_f16<<<dim3(SEQ/128, NH), 256, FL_SMEM>>>(hid, z);

    // 3) output projection (fp32 out)
    gemm_f16<false><<<dim3(MODEL/128, SEQ/128), 256, GEMM_SMEM>>>(
        z, wp, b_proj, out, SEQ, MODEL, MODEL);
}

// round 14
// speedup vs baseline: 3.2017x; 1.0955x over previous
#include <cuda_runtime.h>
#include <cuda_fp16.h>
#include <math.h>
#include <stdint.h>

#define SEQ   4096
#define MODEL 2048
#define NH    16
#define HD    128
#define QKV_N (3*MODEL)
#define KB_MODEL (MODEL/16)   // 128

// Scratch (__device__ globals: allocation-free rule)
// Fragment-layout buffers: chunk = uint4 per (tile16x16, lane)
__device__ uint4  g_xf [(size_t)(SEQ/16)   * KB_MODEL * 32];  // x    A-frags
__device__ uint4  g_waf[(size_t)(QKV_N/16) * KB_MODEL * 32];  // w_attn B-frags
__device__ uint4  g_wpf[(size_t)(MODEL/16) * KB_MODEL * 32];  // w_proj B-frags
__device__ uint4  g_zf [(size_t)(SEQ/16)   * KB_MODEL * 32];  // z    A-frags
__device__ __half g_hidden[(size_t)SEQ * QKV_N];              // QKV out (row layout)

__device__ __forceinline__ uint32_t pack_h2(float a, float b) {
    __half2 h = __floats2half2_rn(a, b);
    return reinterpret_cast<uint32_t&>(h);
}
__device__ __forceinline__ void mma_f16(float* c, const uint32_t* a,
                                        uint32_t b0, uint32_t b1) {
    asm volatile(
        "mma.sync.aligned.m16n8k16.row.col.f32.f16.f16.f32 "
        "{%0,%1,%2,%3}, {%4,%5,%6,%7}, {%8,%9}, {%0,%1,%2,%3};\n"
        : "+f"(c[0]), "+f"(c[1]), "+f"(c[2]), "+f"(c[3])
        : "r"(a[0]), "r"(a[1]), "r"(a[2]), "r"(a[3]), "r"(b0), "r"(b1));
}
__device__ __forceinline__ void ldsm4_t(uint32_t* r, uint32_t addr) {
    asm volatile("ldmatrix.sync.aligned.m8n8.x4.trans.shared.b16 {%0,%1,%2,%3}, [%4];"
        : "=r"(r[0]), "=r"(r[1]), "=r"(r[2]), "=r"(r[3]) : "r"(addr));
}
__device__ __forceinline__ void cp16(uint32_t dst, const void* src) {
    asm volatile("cp.async.cg.shared.global [%0], [%1], 16;\n" :: "r"(dst), "l"(src));
}
__device__ __forceinline__ void cp_commit() { asm volatile("cp.async.commit_group;\n"); }
template<int N> __device__ __forceinline__ void cp_wait() {
    asm volatile("cp.async.wait_group %0;\n" :: "n"(N));
}
__device__ __forceinline__ uint32_t smem_u32(const void* p) {
    uint32_t a;
    asm("{ .reg .u64 t; cvta.to.shared.u64 t, %1; cvt.u32.u64 %0, t; }"
        : "=r"(a) : "l"(p));
    return a;
}

// ---------------------------------------------------------------------------
// Prep: pack x (fp32 [SEQ][MODEL]) into A-fragment layout.
// chunk(mb, kb, lane=(ra,kq)) = {a0,a1,a2,a3} of mma.m16n8k16.
// ---------------------------------------------------------------------------
__global__ void pack_a(const float* __restrict__ x, uint4* __restrict__ out) {
    __shared__ float sA[16][132];
    int cb = blockIdx.x;             // 128-col chunk (0..15)
    int mb = blockIdx.y;             // 16-row tile  (0..255)
    int tid = threadIdx.x;
    #pragma unroll
    for (int i = 0; i < 8; i++) {
        int id = tid + 256*i;
        int r = id >> 7, c = id & 127;
        sA[r][c] = x[(size_t)(mb*16 + r)*MODEL + cb*128 + c];
    }
    __syncthreads();
    int t = tid >> 5, lane = tid & 31, ra = lane >> 2, kq = lane & 3;
    int c0 = t*16;
    uint4 v;
    v.x = pack_h2(sA[ra][c0 + 2*kq],       sA[ra][c0 + 2*kq + 1]);
    v.y = pack_h2(sA[ra+8][c0 + 2*kq],     sA[ra+8][c0 + 2*kq + 1]);
    v.z = pack_h2(sA[ra][c0 + 8 + 2*kq],   sA[ra][c0 + 9 + 2*kq]);
    v.w = pack_h2(sA[ra+8][c0 + 8 + 2*kq], sA[ra+8][c0 + 9 + 2*kq]);
    out[((size_t)mb*KB_MODEL + cb*8 + t)*32 + lane] = v;
}

// ---------------------------------------------------------------------------
// Prep: pack weight w (fp32 [K][N]) into B-fragment layout (implicit transpose).
// chunk(nb, kb, lane) = {b0(ni even), b1(ni even), b0(ni odd), b1(ni odd)}.
// ---------------------------------------------------------------------------
__global__ void pack_b(const float* __restrict__ w, uint4* __restrict__ out,
                       int Ncols, int Krows) {
    __shared__ float tile[32][33];   // tile[k][n]
    int n0c = blockIdx.x * 32, k0 = blockIdx.y * 32;
    int tx = threadIdx.x, ty = threadIdx.y;
    #pragma unroll
    for (int i = 0; i < 32; i += 8)
        tile[ty + i][tx] = w[(size_t)(k0 + ty + i)*Ncols + n0c + tx];
    __syncthreads();
    int tid = ty*32 + tx;
    int sub = tid >> 5;
    if (sub < 4) {
        int nbl = sub & 1, kbl = sub >> 1;
        int lane = tid & 31, ra = lane >> 2, kq = lane & 3;
        int kk0 = kbl*16, nn0 = nbl*16;
        uint4 v;
        v.x = pack_h2(tile[kk0 + 2*kq][nn0 + ra],       tile[kk0 + 2*kq + 1][nn0 + ra]);
        v.y = pack_h2(tile[kk0 + 8 + 2*kq][nn0 + ra],   tile[kk0 + 9 + 2*kq][nn0 + ra]);
        v.z = pack_h2(tile[kk0 + 2*kq][nn0 + 8 + ra],   tile[kk0 + 2*kq + 1][nn0 + 8 + ra]);
        v.w = pack_h2(tile[kk0 + 8 + 2*kq][nn0 + 8 + ra], tile[kk0 + 9 + 2*kq][nn0 + 8 + ra]);
        int nb_g = (n0c >> 4) + nbl;
        int kb_g = (k0 >> 4) + kbl;
        out[((size_t)nb_g*(Krows >> 4) + kb_g)*32 + lane] = v;
    }
}

// ---------------------------------------------------------------------------
// fp16 GEMM on pre-packed fragments: C[:,N] = A @ B^T + bias.
// 128x128 tile, BK=32, 256 thr (2x4 warps, 64x32 warp tile), cp.async 4-stage,
// 2 CTAs/SM. Fragment loads are 12 LDS.128 per warp-iter (conflict-free).
// ---------------------------------------------------------------------------
#define TGS 4
#define STAGE_BYTES 16384            // 8KB A-frags + 8KB B-frags
#define A_BYTES 8192
#define GEMM_SMEM (TGS*STAGE_BYTES)  // 64 KB

template<bool OUT_HALF>
__global__ __launch_bounds__(256, 2) void gemm_f16(
    const uint4* __restrict__ Af, const uint4* __restrict__ Bf,
    const float* __restrict__ bias, void* __restrict__ Cv,
    int N, int KB)
{
    extern __shared__ char gsm[];
    const int tid  = threadIdx.x;
    const int lane = tid & 31;
    const int warp = tid >> 5;
    const int kq   = lane & 3;
    const int mbw = (warp >> 2) * 4;     // warp m16-block base (0 or 4)
    const int nbw = (warp & 3) * 2;      // warp n16-block base (0,2,4,6)
    const int n0  = (warp & 3) * 32;
    const int mb0 = blockIdx.y * 8, nb0 = blockIdx.x * 8;
    const int row0 = blockIdx.y * 128, col0 = blockIdx.x * 128;

    uint32_t asS = (uint32_t)__cvta_generic_to_shared(gsm);
    const int niter = KB >> 1;

    auto issue = [&](int t) {
        uint32_t sb = asS + (uint32_t)(t & (TGS-1)) * STAGE_BYTES;
        #pragma unroll
        for (int j = 0; j < 2; j++) {
            int c = tid + 256*j;
            int bl = c >> 6, kkb = (c >> 5) & 1, ln = c & 31;
            cp16(sb + (uint32_t)c*16u,
                 Af + ((size_t)(mb0 + bl)*KB + 2*t + kkb)*32 + ln);
            cp16(sb + A_BYTES + (uint32_t)c*16u,
                 Bf + ((size_t)(nb0 + bl)*KB + 2*t + kkb)*32 + ln);
        }
        cp_commit();
    };

    #pragma unroll
    for (int s = 0; s < TGS - 1; s++) issue(s);

    float c[4][4][4];
    #pragma unroll
    for (int mi = 0; mi < 4; mi++)
        #pragma unroll
        for (int ni = 0; ni < 4; ni++)
            #pragma unroll
            for (int r = 0; r < 4; r++) c[mi][ni][r] = 0.f;

    for (int i = 0; i < niter; i++) {
        cp_wait<TGS-2>();
        __syncthreads();

        const uint4* Ab = (const uint4*)(gsm + (size_t)(i & (TGS-1)) * STAGE_BYTES);
        const uint4* Bb = Ab + (A_BYTES/16);

        // ---- all fragments via LDS.128 (12 loads) ----
        uint4 af[2][4];
        uint4 bf[2][2];
        #pragma unroll
        for (int kk = 0; kk < 2; kk++) {
            #pragma unroll
            for (int mi = 0; mi < 4; mi++)
                af[kk][mi] = Ab[((mbw + mi)*2 + kk)*32 + lane];
            #pragma unroll
            for (int nbi = 0; nbi < 2; nbi++)
                bf[kk][nbi] = Bb[((nbw + nbi)*2 + kk)*32 + lane];
        }

        // next-stage global prefetch
        if (i + TGS - 1 < niter) issue(i + TGS - 1);
        else                     cp_commit();

        // ---- 32 MMAs back-to-back ----
        #pragma unroll
        for (int kk = 0; kk < 2; kk++)
            #pragma unroll
            for (int nbi = 0; nbi < 2; nbi++) {
                #pragma unroll
                for (int mi = 0; mi < 4; mi++)
                    mma_f16(c[mi][2*nbi], (const uint32_t*)&af[kk][mi],
                            bf[kk][nbi].x, bf[kk][nbi].y);
                #pragma unroll
                for (int mi = 0; mi < 4; mi++)
                    mma_f16(c[mi][2*nbi+1], (const uint32_t*)&af[kk][mi],
                            bf[kk][nbi].z, bf[kk][nbi].w);
            }
    }

    const int ra = lane >> 2;
    #pragma unroll
    for (int ni = 0; ni < 4; ni++) {
        int cc = col0 + n0 + ni*8 + 2*kq;
        float2 bb = *(const float2*)(bias + cc);
        #pragma unroll
        for (int mi = 0; mi < 4; mi++) {
            int r = row0 + mbw*16 + mi*16 + ra;
            float o0 = c[mi][ni][0] + bb.x, o1 = c[mi][ni][1] + bb.y;
            float o2 = c[mi][ni][2] + bb.x, o3 = c[mi][ni][3] + bb.y;
            if (OUT_HALF) {
                uint32_t* C32 = (uint32_t*)Cv;
                C32[(size_t)r * (N>>1) + (cc>>1)]       = pack_h2(o0, o1);
                C32[(size_t)(r + 8) * (N>>1) + (cc>>1)] = pack_h2(o2, o3);
            } else {
                float* C = (float*)Cv;
                *(float2*)(C + (size_t)r * N + cc)       = make_float2(o0, o1);
                *(float2*)(C + (size_t)(r + 8) * N + cc) = make_float2(o2, o3);
            }
        }
    }
}

// ---------------------------------------------------------------------------
// fp16 flash attention (causal) — R13 core; epilogue now writes z directly in
// A-fragment layout (accumulator layout == A-frag layout, 1 uint4 store/tile).
// ---------------------------------------------------------------------------
#define KS 68                            // u32/row: 64 data + 4 pad
#define VS 68
#define PS 36                            // u32/row: 32 data + 4 pad
#define FL_SMEM ((2*64*KS + 2*64*VS + 128*PS)*4)   // 88 KB

__global__ __launch_bounds__(256, 1) void flash_f16(
    const __half* __restrict__ hidden, uint4* __restrict__ zf)
{
    extern __shared__ uint32_t sm[];
    uint32_t* Ks = sm;                    // [2][64][KS]
    uint32_t* Vs = Ks + 2*64*KS;          // [2][64][VS]
    uint32_t* Ps = Vs + 2*64*VS;          // [128][PS]

    const uint32_t* hid32 = (const uint32_t*)hidden;
    const int Qw = QKV_N >> 1;            // u32 per hidden row

    const int h    = blockIdx.y;
    const int qb   = (int)(gridDim.x - 1) - (int)blockIdx.x;  // heavy first
    const int tid  = threadIdx.x;
    const int lane = tid & 31;
    const int warp = tid >> 5;
    const int m0   = warp * 16;
    const int ra   = lane >> 2;
    const int kq   = lane & 3;
    const float scale = 0.08838834764831845f;  // 1/sqrt(128)

    uint32_t asK = smem_u32(Ks);
    uint32_t asV = smem_u32(Vs);
    const int hoff = (MODEL >> 1) + (h*HD >> 1);

    auto load_tile = [&](int t) {
        uint32_t kb_ = asK + (uint32_t)(t & 1) * 64u*KS*4u;
        uint32_t vb_ = asV + (uint32_t)(t & 1) * 64u*VS*4u;
        #pragma unroll
        for (int i = 0; i < 4; i++) {
            int idx = tid + 256*i;
            int r = idx >> 4, c = idx & 15;
            const uint32_t* kp = hid32 + (size_t)(t*64 + r) * Qw + hoff + c*4;
            cp16(kb_ + (uint32_t)(r*KS + c*4)*4u, kp);
            cp16(vb_ + (uint32_t)(r*VS + c*4)*4u, kp + (MODEL >> 1));
        }
        cp_commit();
    };

    uint32_t qf[8][4];
    {
        const uint32_t* qp0 = hid32 + (size_t)(qb*128 + m0 + ra) * Qw + (h*HD >> 1);
        const uint32_t* qp1 = qp0 + (size_t)8 * Qw;
        #pragma unroll
        for (int i = 0; i < 8; i++) {
            qf[i][0] = qp0[i*8 + kq];
            qf[i][1] = qp1[i*8 + kq];
            qf[i][2] = qp0[i*8 + kq + 4];
            qf[i][3] = qp1[i*8 + kq + 4];
        }
    }

    float m_a = -1e30f, m_b = -1e30f, l_a = 0.f, l_b = 0.f;
    float o[16][4];
    #pragma unroll
    for (int ni = 0; ni < 16; ni++)
        o[ni][0] = o[ni][1] = o[ni][2] = o[ni][3] = 0.f;

    const int qr_a = qb*128 + m0 + ra;
    const int nkb  = 2*qb + 2;

    load_tile(0);
    load_tile(1);

    for (int kb = 0; kb < nkb; kb++) {
        cp_wait<1>();
        __syncthreads();

        const uint32_t* Kb = Ks + (kb & 1)*64*KS;
        uint32_t vb_byte = asV + (uint32_t)(kb & 1)*64u*VS*4u;

        float s[8][4];
        #pragma unroll
        for (int n = 0; n < 8; n++) s[n][0] = s[n][1] = s[n][2] = s[n][3] = 0.f;

        #pragma unroll
        for (int i = 0; i < 8; i++) {
            #pragma unroll
            for (int n = 0; n < 8; n++) {
                const uint32_t* kp2 = Kb + (n*8 + ra)*KS + i*8 + kq;
                mma_f16(s[n], qf[i], kp2[0], kp2[4]);
            }
        }

        #pragma unroll
        for (int n = 0; n < 8; n++) {
            s[n][0] *= scale; s[n][1] *= scale;
            s[n][2] *= scale; s[n][3] *= scale;
        }

        if (kb >= 2*qb) {
            #pragma unroll
            for (int n = 0; n < 8; n++) {
                int col = kb*64 + n*8 + 2*kq;
                if (col     > qr_a)     s[n][0] = -1e30f;
                if (col + 1 > qr_a)     s[n][1] = -1e30f;
                if (col     > qr_a + 8) s[n][2] = -1e30f;
                if (col + 1 > qr_a + 8) s[n][3] = -1e30f;
            }
        }

        float mxa = -1e30f, mxb = -1e30f;
        #pragma unroll
        for (int n = 0; n < 8; n++) {
            mxa = fmaxf(mxa, fmaxf(s[n][0], s[n][1]));
            mxb = fmaxf(mxb, fmaxf(s[n][2], s[n][3]));
        }
        mxa = fmaxf(mxa, __shfl_xor_sync(0xffffffffu, mxa, 1));
        mxa = fmaxf(mxa, __shfl_xor_sync(0xffffffffu, mxa, 2));
        mxb = fmaxf(mxb, __shfl_xor_sync(0xffffffffu, mxb, 1));
        mxb = fmaxf(mxb, __shfl_xor_sync(0xffffffffu, mxb, 2));

        float mna = fmaxf(m_a, mxa), mnb = fmaxf(m_b, mxb);
        float alpha_a = __expf(m_a - mna), alpha_b = __expf(m_b - mnb);
        float suma = 0.f, sumb = 0.f;
        #pragma unroll
        for (int n = 0; n < 8; n++) {
            float p0 = __expf(s[n][0] - mna), p1 = __expf(s[n][1] - mna);
            float p2 = __expf(s[n][2] - mnb), p3 = __expf(s[n][3] - mnb);
            suma += p0 + p1; sumb += p2 + p3;
            Ps[(m0 + ra)*PS + n*4 + kq]     = pack_h2(p0, p1);
            Ps[(m0 + ra + 8)*PS + n*4 + kq] = pack_h2(p2, p3);
        }
        suma += __shfl_xor_sync(0xffffffffu, suma, 1);
        suma += __shfl_xor_sync(0xffffffffu, suma, 2);
        sumb += __shfl_xor_sync(0xffffffffu, sumb, 1);
        sumb += __shfl_xor_sync(0xffffffffu, sumb, 2);
        l_a = l_a * alpha_a + suma;
        l_b = l_b * alpha_b + sumb;
        m_a = mna; m_b = mnb;
        #pragma unroll
        for (int ni = 0; ni < 16; ni++) {
            o[ni][0] *= alpha_a; o[ni][1] *= alpha_a;
            o[ni][2] *= alpha_b; o[ni][3] *= alpha_b;
        }
        __syncwarp();

        const int g  = lane >> 3;
        const int rr = lane & 7;
        #pragma unroll
        for (int s4 = 0; s4 < 4; s4++) {
            uint32_t a[4];
            const uint32_t* pp = Ps + (m0 + ra)*PS + s4*8 + kq;
            a[0] = pp[0];
            a[1] = pp[8*PS];
            a[2] = pp[4];
            a[3] = pp[8*PS + 4];
            #pragma unroll
            for (int nn = 0; nn < 8; nn++) {
                uint32_t bfv[4];
                uint32_t addr = vb_byte +
                    (uint32_t)((s4*16 + (g & 1)*8 + rr)*VS + nn*8 + (g >> 1)*4) * 4u;
                ldsm4_t(bfv, addr);
                mma_f16(o[2*nn],     a, bfv[0], bfv[1]);
                mma_f16(o[2*nn + 1], a, bfv[2], bfv[3]);
            }
        }

        __syncthreads();
        if (kb + 2 < nkb) load_tile(kb + 2);
        else              cp_commit();
    }

    // ---- normalize + write z in A-fragment layout (proj GEMM fast path) ----
    float inva = 1.f / l_a, invb = 1.f / l_b;
    int mb_g = qb*8 + warp;
    #pragma unroll
    for (int j = 0; j < 8; j++) {
        int kb_g = h*8 + j;
        uint4 v;
        v.x = pack_h2(o[2*j][0]*inva,   o[2*j][1]*inva);
        v.y = pack_h2(o[2*j][2]*invb,   o[2*j][3]*invb);
        v.z = pack_h2(o[2*j+1][0]*inva, o[2*j+1][1]*inva);
        v.w = pack_h2(o[2*j+1][2]*invb, o[2*j+1][3]*invb);
        zf[((size_t)mb_g*KB_MODEL + kb_g)*32 + lane] = v;
    }
}

// ---------------------------------------------------------------------------
extern "C" void kernel_launch(void* const* d_in, const int* in_sizes, int n_in,
                              void* d_out, int out_size)
{
    const float* x      = (const float*)d_in[0];
    const float* w_attn = (const float*)d_in[1];
    const float* b_attn = (const float*)d_in[2];
    const float* w_proj = (const float*)d_in[3];
    const float* b_proj = (const float*)d_in[4];
    float* out = (float*)d_out;

    uint4 *xf, *waf, *wpf, *zf;
    __half* hid;
    cudaGetSymbolAddress((void**)&xf,  g_xf);
    cudaGetSymbolAddress((void**)&waf, g_waf);
    cudaGetSymbolAddress((void**)&wpf, g_wpf);
    cudaGetSymbolAddress((void**)&zf,  g_zf);
    cudaGetSymbolAddress((void**)&hid, g_hidden);

    cudaFuncSetAttribute(gemm_f16<true>,
                         cudaFuncAttributeMaxDynamicSharedMemorySize, GEMM_SMEM);
    cudaFuncSetAttribute(gemm_f16<false>,
                         cudaFuncAttributeMaxDynamicSharedMemorySize, GEMM_SMEM);
    cudaFuncSetAttribute(flash_f16,
                         cudaFuncAttributeMaxDynamicSharedMemorySize, FL_SMEM);

    // 0) prep: pack x into A-frags; weights into B-frags (implicit transpose)
    pack_a<<<dim3(MODEL/128, SEQ/16), 256>>>(x, xf);
    pack_b<<<dim3(QKV_N/32, MODEL/32), dim3(32, 8)>>>(w_attn, waf, QKV_N, MODEL);
    pack_b<<<dim3(MODEL/32, MODEL/32), dim3(32, 8)>>>(w_proj, wpf, MODEL, MODEL);

    // 1) QKV projection (fp16 row-layout out feeds flash)
    gemm_f16<true><<<dim3(QKV_N/128, SEQ/128), 256, GEMM_SMEM>>>(
        xf, waf, b_attn, hid, QKV_N, KB_MODEL);

    // 2) causal multi-head attention (writes z in A-frag layout)
    flash_f16<<<dim3(SEQ/128, NH), 256, FL_SMEM>>>(hid, zf);

    // 3) output projection (fp32 out)
    gemm_f16<false><<<dim3(MODEL/128, SEQ/128), 256, GEMM_SMEM>>>(
        zf, wpf, b_proj, out, MODEL, KB_MODEL);
}

// round 15
// speedup vs baseline: 3.2758x; 1.0231x over previous
#include <cuda_runtime.h>
#include <cuda_fp16.h>
#include <math.h>
#include <stdint.h>

#define SEQ   4096
#define MODEL 2048
#define NH    16
#define HD    128
#define QKV_N (3*MODEL)
#define KB_MODEL (MODEL/16)   // 128

// Scratch (__device__ globals: allocation-free rule)
__device__ uint4  g_xf [(size_t)(SEQ/16)   * KB_MODEL * 32];  // x    A-frags
__device__ uint4  g_waf[(size_t)(QKV_N/16) * KB_MODEL * 32];  // w_attn B-frags
__device__ uint4  g_wpf[(size_t)(MODEL/16) * KB_MODEL * 32];  // w_proj B-frags
__device__ uint4  g_zf [(size_t)(SEQ/16)   * KB_MODEL * 32];  // z    A-frags
__device__ __half g_hidden[(size_t)SEQ * QKV_N];              // QKV out (row layout)

__device__ __forceinline__ uint32_t pack_h2(float a, float b) {
    __half2 h = __floats2half2_rn(a, b);
    return reinterpret_cast<uint32_t&>(h);
}
__device__ __forceinline__ void mma_f16(float* c, const uint32_t* a,
                                        uint32_t b0, uint32_t b1) {
    asm volatile(
        "mma.sync.aligned.m16n8k16.row.col.f32.f16.f16.f32 "
        "{%0,%1,%2,%3}, {%4,%5,%6,%7}, {%8,%9}, {%0,%1,%2,%3};\n"
        : "+f"(c[0]), "+f"(c[1]), "+f"(c[2]), "+f"(c[3])
        : "r"(a[0]), "r"(a[1]), "r"(a[2]), "r"(a[3]), "r"(b0), "r"(b1));
}
__device__ __forceinline__ void ldsm4_t(uint32_t* r, uint32_t addr) {
    asm volatile("ldmatrix.sync.aligned.m8n8.x4.trans.shared.b16 {%0,%1,%2,%3}, [%4];"
        : "=r"(r[0]), "=r"(r[1]), "=r"(r[2]), "=r"(r[3]) : "r"(addr));
}
__device__ __forceinline__ void lds128(uint4& v, uint32_t addr) {
    asm volatile("ld.shared.v4.u32 {%0,%1,%2,%3}, [%4];"
        : "=r"(v.x), "=r"(v.y), "=r"(v.z), "=r"(v.w) : "r"(addr));
}
__device__ __forceinline__ void cp16(uint32_t dst, const void* src) {
    asm volatile("cp.async.cg.shared.global [%0], [%1], 16;\n" :: "r"(dst), "l"(src));
}
__device__ __forceinline__ void cp_commit() { asm volatile("cp.async.commit_group;\n"); }
template<int N> __device__ __forceinline__ void cp_wait() {
    asm volatile("cp.async.wait_group %0;\n" :: "n"(N));
}
__device__ __forceinline__ uint32_t smem_u32(const void* p) {
    uint32_t a;
    asm("{ .reg .u64 t; cvta.to.shared.u64 t, %1; cvt.u32.u64 %0, t; }"
        : "=r"(a) : "l"(p));
    return a;
}

// ---------------------------------------------------------------------------
// Prep: pack x (fp32 [SEQ][MODEL]) into A-fragment layout.
// ---------------------------------------------------------------------------
__global__ void pack_a(const float* __restrict__ x, uint4* __restrict__ out) {
    __shared__ float sA[16][132];
    int cb = blockIdx.x;             // 128-col chunk
    int mb = blockIdx.y;             // 16-row tile
    int tid = threadIdx.x;
    #pragma unroll
    for (int i = 0; i < 8; i++) {
        int id = tid + 256*i;
        int r = id >> 7, c = id & 127;
        sA[r][c] = x[(size_t)(mb*16 + r)*MODEL + cb*128 + c];
    }
    __syncthreads();
    int t = tid >> 5, lane = tid & 31, ra = lane >> 2, kq = lane & 3;
    int c0 = t*16;
    uint4 v;
    v.x = pack_h2(sA[ra][c0 + 2*kq],       sA[ra][c0 + 2*kq + 1]);
    v.y = pack_h2(sA[ra+8][c0 + 2*kq],     sA[ra+8][c0 + 2*kq + 1]);
    v.z = pack_h2(sA[ra][c0 + 8 + 2*kq],   sA[ra][c0 + 9 + 2*kq]);
    v.w = pack_h2(sA[ra+8][c0 + 8 + 2*kq], sA[ra+8][c0 + 9 + 2*kq]);
    out[((size_t)mb*KB_MODEL + cb*8 + t)*32 + lane] = v;
}

// ---------------------------------------------------------------------------
// Prep: pack weight w (fp32 [K][N]) into B-fragment layout (implicit transpose).
// ---------------------------------------------------------------------------
__global__ void pack_b(const float* __restrict__ w, uint4* __restrict__ out,
                       int Ncols, int Krows) {
    __shared__ float tile[32][33];   // tile[k][n]
    int n0c = blockIdx.x * 32, k0 = blockIdx.y * 32;
    int tx = threadIdx.x, ty = threadIdx.y;
    #pragma unroll
    for (int i = 0; i < 32; i += 8)
        tile[ty + i][tx] = w[(size_t)(k0 + ty + i)*Ncols + n0c + tx];
    __syncthreads();
    int tid = ty*32 + tx;
    int sub = tid >> 5;
    if (sub < 4) {
        int nbl = sub & 1, kbl = sub >> 1;
        int lane = tid & 31, ra = lane >> 2, kq = lane & 3;
        int kk0 = kbl*16, nn0 = nbl*16;
        uint4 v;
        v.x = pack_h2(tile[kk0 + 2*kq][nn0 + ra],       tile[kk0 + 2*kq + 1][nn0 + ra]);
        v.y = pack_h2(tile[kk0 + 8 + 2*kq][nn0 + ra],   tile[kk0 + 9 + 2*kq][nn0 + ra]);
        v.z = pack_h2(tile[kk0 + 2*kq][nn0 + 8 + ra],   tile[kk0 + 2*kq + 1][nn0 + 8 + ra]);
        v.w = pack_h2(tile[kk0 + 8 + 2*kq][nn0 + 8 + ra], tile[kk0 + 9 + 2*kq][nn0 + 8 + ra]);
        int nb_g = (n0c >> 4) + nbl;
        int kb_g = (k0 >> 4) + kbl;
        out[((size_t)nb_g*(Krows >> 4) + kb_g)*32 + lane] = v;
    }
}

// ---------------------------------------------------------------------------
// fp16 GEMM on pre-packed fragments. 128x128 tile, BK=32/stage, GS=6 ring,
// TWO stages per barrier (32 sync points for K=2048). 256 thr, 2 CTAs/SM.
// Fragment loads: 12 LDS.128 per warp-stage on precomputed u32 addresses.
// ---------------------------------------------------------------------------
#define TGS 6
#define STAGE_BYTES 16384            // 8KB A-frags + 8KB B-frags
#define A_BYTES 8192
#define GEMM_SMEM (TGS*STAGE_BYTES)  // 96 KB

template<bool OUT_HALF>
__global__ __launch_bounds__(256, 2) void gemm_f16(
    const uint4* __restrict__ Af, const uint4* __restrict__ Bf,
    const float* __restrict__ bias, void* __restrict__ Cv,
    int N, int KB)
{
    extern __shared__ char gsm[];
    const int tid  = threadIdx.x;
    const int lane = tid & 31;
    const int warp = tid >> 5;
    const int kq   = lane & 3;
    const int mbw = (warp >> 2) * 4;
    const int nbw = (warp & 3) * 2;
    const int n0  = (warp & 3) * 32;
    const int mb0 = blockIdx.y * 8, nb0 = blockIdx.x * 8;
    const int row0 = blockIdx.y * 128, col0 = blockIdx.x * 128;

    uint32_t asS = (uint32_t)__cvta_generic_to_shared(gsm);
    // loop-invariant per-thread fragment base addresses (bytes, within stage)
    const uint32_t aBase = (uint32_t)((mbw*2)*32 + lane) * 16u;
    const uint32_t bBase = (uint32_t)A_BYTES + (uint32_t)((nbw*2)*32 + lane) * 16u;
    const int niter = KB >> 1;

    auto issue = [&](int t) {
        uint32_t sb = asS + (uint32_t)(t % TGS) * STAGE_BYTES;
        #pragma unroll
        for (int j = 0; j < 2; j++) {
            int c = tid + 256*j;
            int bl = c >> 6, kkb = (c >> 5) & 1, ln = c & 31;
            cp16(sb + (uint32_t)c*16u,
                 Af + ((size_t)(mb0 + bl)*KB + 2*t + kkb)*32 + ln);
            cp16(sb + A_BYTES + (uint32_t)c*16u,
                 Bf + ((size_t)(nb0 + bl)*KB + 2*t + kkb)*32 + ln);
        }
        cp_commit();
    };

    #pragma unroll
    for (int s = 0; s < 4; s++) issue(s);

    float c[4][4][4];
    #pragma unroll
    for (int mi = 0; mi < 4; mi++)
        #pragma unroll
        for (int ni = 0; ni < 4; ni++)
            #pragma unroll
            for (int r = 0; r < 4; r++) c[mi][ni][r] = 0.f;

    const int npairs = niter >> 1;
    for (int p = 0; p < npairs; p++) {
        cp_wait<2>();            // stages <= 2p+1 resident
        __syncthreads();

        #pragma unroll
        for (int h2 = 0; h2 < 2; h2++) {
            int s = 2*p + h2;
            uint32_t sb = asS + (uint32_t)(s % TGS) * STAGE_BYTES;

            // ---- fragments via 12 LDS.128 on u32 addresses ----
            uint4 af[2][4];
            uint4 bf[2][2];
            #pragma unroll
            for (int kk = 0; kk < 2; kk++) {
                #pragma unroll
                for (int mi = 0; mi < 4; mi++)
                    lds128(af[kk][mi], sb + aBase + (uint32_t)(mi*2 + kk)*32u*16u);
                #pragma unroll
                for (int nbi = 0; nbi < 2; nbi++)
                    lds128(bf[kk][nbi], sb + bBase + (uint32_t)(nbi*2 + kk)*32u*16u);
            }

            // prefetch stage s+4 (empty commit past the end keeps counts exact)
            if (s + 4 < niter) issue(s + 4);
            else               cp_commit();

            // ---- 32 MMAs ----
            #pragma unroll
            for (int kk = 0; kk < 2; kk++)
                #pragma unroll
                for (int nbi = 0; nbi < 2; nbi++) {
                    #pragma unroll
                    for (int mi = 0; mi < 4; mi++)
                        mma_f16(c[mi][2*nbi], (const uint32_t*)&af[kk][mi],
                                bf[kk][nbi].x, bf[kk][nbi].y);
                    #pragma unroll
                    for (int mi = 0; mi < 4; mi++)
                        mma_f16(c[mi][2*nbi+1], (const uint32_t*)&af[kk][mi],
                                bf[kk][nbi].z, bf[kk][nbi].w);
                }
        }
    }

    const int ra = lane >> 2;
    #pragma unroll
    for (int ni = 0; ni < 4; ni++) {
        int cc = col0 + n0 + ni*8 + 2*kq;
        float2 bb = *(const float2*)(bias + cc);
        #pragma unroll
        for (int mi = 0; mi < 4; mi++) {
            int r = row0 + mbw*16 + mi*16 + ra;
            float o0 = c[mi][ni][0] + bb.x, o1 = c[mi][ni][1] + bb.y;
            float o2 = c[mi][ni][2] + bb.x, o3 = c[mi][ni][3] + bb.y;
            if (OUT_HALF) {
                uint32_t* C32 = (uint32_t*)Cv;
                C32[(size_t)r * (N>>1) + (cc>>1)]       = pack_h2(o0, o1);
                C32[(size_t)(r + 8) * (N>>1) + (cc>>1)] = pack_h2(o2, o3);
            } else {
                float* C = (float*)Cv;
                *(float2*)(C + (size_t)r * N + cc)       = make_float2(o0, o1);
                *(float2*)(C + (size_t)(r + 8) * N + cc) = make_float2(o2, o3);
            }
        }
    }
}

// ---------------------------------------------------------------------------
// fp16 flash attention (causal) — unchanged from R14 (writes z in A-frag layout).
// ---------------------------------------------------------------------------
#define KS 68
#define VS 68
#define PS 36
#define FL_SMEM ((2*64*KS + 2*64*VS + 128*PS)*4)   // 88 KB

__global__ __launch_bounds__(256, 1) void flash_f16(
    const __half* __restrict__ hidden, uint4* __restrict__ zf)
{
    extern __shared__ uint32_t sm[];
    uint32_t* Ks = sm;
    uint32_t* Vs = Ks + 2*64*KS;
    uint32_t* Ps = Vs + 2*64*VS;

    const uint32_t* hid32 = (const uint32_t*)hidden;
    const int Qw = QKV_N >> 1;

    const int h    = blockIdx.y;
    const int qb   = (int)(gridDim.x - 1) - (int)blockIdx.x;
    const int tid  = threadIdx.x;
    const int lane = tid & 31;
    const int warp = tid >> 5;
    const int m0   = warp * 16;
    const int ra   = lane >> 2;
    const int kq   = lane & 3;
    const float scale = 0.08838834764831845f;

    uint32_t asK = smem_u32(Ks);
    uint32_t asV = smem_u32(Vs);
    const int hoff = (MODEL >> 1) + (h*HD >> 1);

    auto load_tile = [&](int t) {
        uint32_t kb_ = asK + (uint32_t)(t & 1) * 64u*KS*4u;
        uint32_t vb_ = asV + (uint32_t)(t & 1) * 64u*VS*4u;
        #pragma unroll
        for (int i = 0; i < 4; i++) {
            int idx = tid + 256*i;
            int r = idx >> 4, c = idx & 15;
            const uint32_t* kp = hid32 + (size_t)(t*64 + r) * Qw + hoff + c*4;
            cp16(kb_ + (uint32_t)(r*KS + c*4)*4u, kp);
            cp16(vb_ + (uint32_t)(r*VS + c*4)*4u, kp + (MODEL >> 1));
        }
        cp_commit();
    };

    uint32_t qf[8][4];
    {
        const uint32_t* qp0 = hid32 + (size_t)(qb*128 + m0 + ra) * Qw + (h*HD >> 1);
        const uint32_t* qp1 = qp0 + (size_t)8 * Qw;
        #pragma unroll
        for (int i = 0; i < 8; i++) {
            qf[i][0] = qp0[i*8 + kq];
            qf[i][1] = qp1[i*8 + kq];
            qf[i][2] = qp0[i*8 + kq + 4];
            qf[i][3] = qp1[i*8 + kq + 4];
        }
    }

    float m_a = -1e30f, m_b = -1e30f, l_a = 0.f, l_b = 0.f;
    float o[16][4];
    #pragma unroll
    for (int ni = 0; ni < 16; ni++)
        o[ni][0] = o[ni][1] = o[ni][2] = o[ni][3] = 0.f;

    const int qr_a = qb*128 + m0 + ra;
    const int nkb  = 2*qb + 2;

    load_tile(0);
    load_tile(1);

    for (int kb = 0; kb < nkb; kb++) {
        cp_wait<1>();
        __syncthreads();

        const uint32_t* Kb = Ks + (kb & 1)*64*KS;
        uint32_t vb_byte = asV + (uint32_t)(kb & 1)*64u*VS*4u;

        float s[8][4];
        #pragma unroll
        for (int n = 0; n < 8; n++) s[n][0] = s[n][1] = s[n][2] = s[n][3] = 0.f;

        #pragma unroll
        for (int i = 0; i < 8; i++) {
            #pragma unroll
            for (int n = 0; n < 8; n++) {
                const uint32_t* kp2 = Kb + (n*8 + ra)*KS + i*8 + kq;
                mma_f16(s[n], qf[i], kp2[0], kp2[4]);
            }
        }

        #pragma unroll
        for (int n = 0; n < 8; n++) {
            s[n][0] *= scale; s[n][1] *= scale;
            s[n][2] *= scale; s[n][3] *= scale;
        }

        if (kb >= 2*qb) {
            #pragma unroll
            for (int n = 0; n < 8; n++) {
                int col = kb*64 + n*8 + 2*kq;
                if (col     > qr_a)     s[n][0] = -1e30f;
                if (col + 1 > qr_a)     s[n][1] = -1e30f;
                if (col     > qr_a + 8) s[n][2] = -1e30f;
                if (col + 1 > qr_a + 8) s[n][3] = -1e30f;
            }
        }

        float mxa = -1e30f, mxb = -1e30f;
        #pragma unroll
        for (int n = 0; n < 8; n++) {
            mxa = fmaxf(mxa, fmaxf(s[n][0], s[n][1]));
            mxb = fmaxf(mxb, fmaxf(s[n][2], s[n][3]));
        }
        mxa = fmaxf(mxa, __shfl_xor_sync(0xffffffffu, mxa, 1));
        mxa = fmaxf(mxa, __shfl_xor_sync(0xffffffffu, mxa, 2));
        mxb = fmaxf(mxb, __shfl_xor_sync(0xffffffffu, mxb, 1));
        mxb = fmaxf(mxb, __shfl_xor_sync(0xffffffffu, mxb, 2));

        float mna = fmaxf(m_a, mxa), mnb = fmaxf(m_b, mxb);
        float alpha_a = __expf(m_a - mna), alpha_b = __expf(m_b - mnb);
        float suma = 0.f, sumb = 0.f;
        #pragma unroll
        for (int n = 0; n < 8; n++) {
            float p0 = __expf(s[n][0] - mna), p1 = __expf(s[n][1] - mna);
            float p2 = __expf(s[n][2] - mnb), p3 = __expf(s[n][3] - mnb);
            suma += p0 + p1; sumb += p2 + p3;
            Ps[(m0 + ra)*PS + n*4 + kq]     = pack_h2(p0, p1);
            Ps[(m0 + ra + 8)*PS + n*4 + kq] = pack_h2(p2, p3);
        }
        suma += __shfl_xor_sync(0xffffffffu, suma, 1);
        suma += __shfl_xor_sync(0xffffffffu, suma, 2);
        sumb += __shfl_xor_sync(0xffffffffu, sumb, 1);
        sumb += __shfl_xor_sync(0xffffffffu, sumb, 2);
        l_a = l_a * alpha_a + suma;
        l_b = l_b * alpha_b + sumb;
        m_a = mna; m_b = mnb;
        #pragma unroll
        for (int ni = 0; ni < 16; ni++) {
            o[ni][0] *= alpha_a; o[ni][1] *= alpha_a;
            o[ni][2] *= alpha_b; o[ni][3] *= alpha_b;
        }
        __syncwarp();

        const int g  = lane >> 3;
        const int rr = lane & 7;
        #pragma unroll
        for (int s4 = 0; s4 < 4; s4++) {
            uint32_t a[4];
            const uint32_t* pp = Ps + (m0 + ra)*PS + s4*8 + kq;
            a[0] = pp[0];
            a[1] = pp[8*PS];
            a[2] = pp[4];
            a[3] = pp[8*PS + 4];
            #pragma unroll
            for (int nn = 0; nn < 8; nn++) {
                uint32_t bfv[4];
                uint32_t addr = vb_byte +
                    (uint32_t)((s4*16 + (g & 1)*8 + rr)*VS + nn*8 + (g >> 1)*4) * 4u;
                ldsm4_t(bfv, addr);
                mma_f16(o[2*nn],     a, bfv[0], bfv[1]);
                mma_f16(o[2*nn + 1], a, bfv[2], bfv[3]);
            }
        }

        __syncthreads();
        if (kb + 2 < nkb) load_tile(kb + 2);
        else              cp_commit();
    }

    // ---- normalize + write z in A-fragment layout (proj GEMM fast path) ----
    float inva = 1.f / l_a, invb = 1.f / l_b;
    int mb_g = qb*8 + warp;
    #pragma unroll
    for (int j = 0; j < 8; j++) {
        int kb_g = h*8 + j;
        uint4 v;
        v.x = pack_h2(o[2*j][0]*inva,   o[2*j][1]*inva);
        v.y = pack_h2(o[2*j][2]*invb,   o[2*j][3]*invb);
        v.z = pack_h2(o[2*j+1][0]*inva, o[2*j+1][1]*inva);
        v.w = pack_h2(o[2*j+1][2]*invb, o[2*j+1][3]*invb);
        zf[((size_t)mb_g*KB_MODEL + kb_g)*32 + lane] = v;
    }
}

// ---------------------------------------------------------------------------
extern "C" void kernel_launch(void* const* d_in, const int* in_sizes, int n_in,
                              void* d_out, int out_size)
{
    const float* x      = (const float*)d_in[0];
    const float* w_attn = (const float*)d_in[1];
    const float* b_attn = (const float*)d_in[2];
    const float* w_proj = (const float*)d_in[3];
    const float* b_proj = (const float*)d_in[4];
    float* out = (float*)d_out;

    uint4 *xf, *waf, *wpf, *zf;
    __half* hid;
    cudaGetSymbolAddress((void**)&xf,  g_xf);
    cudaGetSymbolAddress((void**)&waf, g_waf);
    cudaGetSymbolAddress((void**)&wpf, g_wpf);
    cudaGetSymbolAddress((void**)&zf,  g_zf);
    cudaGetSymbolAddress((void**)&hid, g_hidden);

    cudaFuncSetAttribute(gemm_f16<true>,
                         cudaFuncAttributeMaxDynamicSharedMemorySize, GEMM_SMEM);
    cudaFuncSetAttribute(gemm_f16<false>,
                         cudaFuncAttributeMaxDynamicSharedMemorySize, GEMM_SMEM);
    cudaFuncSetAttribute(flash_f16,
                         cudaFuncAttributeMaxDynamicSharedMemorySize, FL_SMEM);

    // 0) prep: pack x into A-frags; weights into B-frags (implicit transpose)
    pack_a<<<dim3(MODEL/128, SEQ/16), 256>>>(x, xf);
    pack_b<<<dim3(QKV_N/32, MODEL/32), dim3(32, 8)>>>(w_attn, waf, QKV_N, MODEL);
    pack_b<<<dim3(MODEL/32, MODEL/32), dim3(32, 8)>>>(w_proj, wpf, MODEL, MODEL);

    // 1) QKV projection (fp16 row-layout out feeds flash)
    gemm_f16<true><<<dim3(QKV_N/128, SEQ/128), 256, GEMM_SMEM>>>(
        xf, waf, b_attn, hid, QKV_N, KB_MODEL);

    // 2) causal multi-head attention (writes z in A-frag layout)
    flash_f16<<<dim3(SEQ/128, NH), 256, FL_SMEM>>>(hid, zf);

    // 3) output projection (fp32 out)
    gemm_f16<false><<<dim3(MODEL/128, SEQ/128), 256, GEMM_SMEM>>>(
        zf, wpf, b_proj, out, MODEL, KB_MODEL);
}